// round 3
// baseline (speedup 1.0000x reference)
#include <cuda_runtime.h>

#define NNODES 50000
#define NEDGES 800000
#define FIN    128
#define BN_EPS 1e-5f

// ---------------- scratch (device globals: no allocs allowed) ----------------
__device__ float g_bufA[NNODES * 128];   // hs = (x@W) * dinv[row]
__device__ float g_bufB[NNODES * 128];   // layer output
__device__ int   g_deg[NNODES];
__device__ int   g_rowptr[NNODES + 1];
__device__ int   g_cursor[NNODES];
__device__ int   g_col[NEDGES];
__device__ float g_dinv[NNODES];

// ---------------- CSR build ----------------
__global__ void zero_deg_k() {
    int i = blockIdx.x * blockDim.x + threadIdx.x;
    if (i < NNODES) g_deg[i] = 0;
}

__global__ void deg_hist_k(const int* __restrict__ ei) {
    int e = blockIdx.x * blockDim.x + threadIdx.x;
    if (e < NEDGES) {
        int dst = ei[NEDGES + e];
        atomicAdd(&g_deg[dst], 1);
    }
}

// single-block chunked Hillis-Steele scan; also emits cursor copy and dinv
__global__ void scan_k() {
    __shared__ int s[1024];
    __shared__ int carry;
    if (threadIdx.x == 0) carry = 0;
    __syncthreads();
    for (int base = 0; base < NNODES; base += 1024) {
        int i = base + threadIdx.x;
        int v = (i < NNODES) ? g_deg[i] : 0;
        s[threadIdx.x] = v;
        __syncthreads();
        #pragma unroll
        for (int off = 1; off < 1024; off <<= 1) {
            int t = (threadIdx.x >= off) ? s[threadIdx.x - off] : 0;
            __syncthreads();
            s[threadIdx.x] += t;
            __syncthreads();
        }
        if (i < NNODES) {
            int o = carry + s[threadIdx.x] - v;   // exclusive
            g_rowptr[i] = o;
            g_cursor[i] = o;
            g_dinv[i]   = rsqrtf(1.0f + (float)v);
        }
        __syncthreads();
        if (threadIdx.x == 0) carry += s[1023];
        __syncthreads();
    }
    if (threadIdx.x == 0) g_rowptr[NNODES] = carry;
}

__global__ void fill_csr_k(const int* __restrict__ ei) {
    int e = blockIdx.x * blockDim.x + threadIdx.x;
    if (e < NEDGES) {
        int src = ei[e];
        int dst = ei[NEDGES + e];
        int pos = atomicAdd(&g_cursor[dst], 1);
        g_col[pos] = src;
    }
}

// ---------------- GEMM: out[row] = (A[row,:] @ W) * dinv[row] ----------------
// A source selected by selA (0=ext, 1=g_bufA, 2=g_bufB); out by selO (1/2).
// BM=64 rows/block, 256 threads, each thread computes 4 x TN outputs. K tiled by 32.
template <int FOUT, int TN>
__global__ __launch_bounds__(256) void gemm_scale_k(
    const float* __restrict__ Aext, int selA, int selO,
    const float* __restrict__ W)
{
    const int TM = 4, BM = 64, KT = 32;
    const int TX = FOUT / TN;   // 16
    __shared__ float As[BM][KT + 1];
    __shared__ float Ws[KT][FOUT];

    const float* A = (selA == 1) ? g_bufA : (selA == 2) ? g_bufB : Aext;
    float* out = (selO == 1) ? g_bufA : g_bufB;

    int tid = threadIdx.x;
    int tx  = tid % TX;          // col group
    int ty  = tid / TX;          // row group (0..15)
    int rb  = blockIdx.x * BM;

    float acc[TM][TN];
    #pragma unroll
    for (int i = 0; i < TM; i++)
        #pragma unroll
        for (int j = 0; j < TN; j++) acc[i][j] = 0.0f;

    for (int kt = 0; kt < FIN; kt += KT) {
        // load A tile (BM x KT)
        #pragma unroll
        for (int t = 0; t < (BM * KT) / 256; t++) {
            int idx = tid + t * 256;
            int r = idx / KT, k = idx % KT;
            int row = rb + r;
            As[r][k] = (row < NNODES) ? A[(size_t)row * FIN + kt + k] : 0.0f;
        }
        // load W tile (KT x FOUT)
        #pragma unroll
        for (int t = 0; t < (KT * FOUT) / 256; t++) {
            int idx = tid + t * 256;
            int k = idx / FOUT, f = idx % FOUT;
            Ws[k][f] = W[(size_t)(kt + k) * FOUT + f];
        }
        __syncthreads();

        #pragma unroll
        for (int k = 0; k < KT; k++) {
            float a[TM], w[TN];
            #pragma unroll
            for (int i = 0; i < TM; i++) a[i] = As[ty * TM + i][k];
            #pragma unroll
            for (int j = 0; j < TN; j++) w[j] = Ws[k][tx * TN + j];
            #pragma unroll
            for (int i = 0; i < TM; i++)
                #pragma unroll
                for (int j = 0; j < TN; j++)
                    acc[i][j] = fmaf(a[i], w[j], acc[i][j]);
        }
        __syncthreads();
    }

    #pragma unroll
    for (int i = 0; i < TM; i++) {
        int row = rb + ty * TM + i;
        if (row < NNODES) {
            float d = g_dinv[row];
            #pragma unroll
            for (int j = 0; j < TN; j++)
                out[(size_t)row * FOUT + tx * TN + j] = acc[i][j] * d;
        }
    }
}

// ---------------- aggregate + bias (+BN+leaky) ----------------
// out[dst] = dinv[dst] * (hs[dst] + sum_{src in N(dst)} hs[src]) + b, then BN+leaky.
// hs source sel (1=g_bufA, 2=g_bufB); out: external pointer if Oext!=null else sel'd.
template <int F, bool BNR>
__global__ __launch_bounds__(128) void agg_k(
    int selH, int selO, float* __restrict__ Oext,
    const float* __restrict__ bias,
    const float* __restrict__ gam, const float* __restrict__ bet,
    const float* __restrict__ mu,  const float* __restrict__ var)
{
    const int PER = 128 / F;
    int dst = blockIdx.x * PER + threadIdx.x / F;
    int f   = threadIdx.x % F;
    if (dst >= NNODES) return;

    const float* hs = (selH == 1) ? g_bufA : g_bufB;
    float* out = Oext ? Oext : ((selO == 1) ? g_bufA : g_bufB);

    int beg = g_rowptr[dst];
    int end = g_rowptr[dst + 1];

    float acc = hs[(size_t)dst * F + f];   // self term (already dinv-scaled)
    int e = beg;
    for (; e + 4 <= end; e += 4) {
        int s0 = g_col[e], s1 = g_col[e + 1], s2 = g_col[e + 2], s3 = g_col[e + 3];
        float a0 = hs[(size_t)s0 * F + f];
        float a1 = hs[(size_t)s1 * F + f];
        float a2 = hs[(size_t)s2 * F + f];
        float a3 = hs[(size_t)s3 * F + f];
        acc += (a0 + a1) + (a2 + a3);
    }
    for (; e < end; e++) acc += hs[(size_t)g_col[e] * F + f];

    float val = acc * g_dinv[dst] + bias[f];
    if (BNR) {
        val = (val - mu[f]) * rsqrtf(var[f] + BN_EPS) * gam[f] + bet[f];
        val = val > 0.0f ? val : 0.1f * val;
    }
    out[(size_t)dst * F + f] = val;
}

// ---------------- launch ----------------
extern "C" void kernel_launch(void* const* d_in, const int* in_sizes, int n_in,
                              void* d_out, int out_size)
{
    const float* x   = (const float*)d_in[0];
    const int*   ei  = (const int*)d_in[1];
    const float* W1 = (const float*)d_in[2];
    const float* b1 = (const float*)d_in[3];
    const float* g1 = (const float*)d_in[4];
    const float* be1= (const float*)d_in[5];
    const float* m1 = (const float*)d_in[6];
    const float* v1 = (const float*)d_in[7];
    const float* W2 = (const float*)d_in[8];
    const float* b2 = (const float*)d_in[9];
    const float* g2 = (const float*)d_in[10];
    const float* be2= (const float*)d_in[11];
    const float* m2 = (const float*)d_in[12];
    const float* v2 = (const float*)d_in[13];
    const float* W3 = (const float*)d_in[14];
    const float* b3 = (const float*)d_in[15];
    float* out = (float*)d_out;

    // graph structure (rebuilt every call: deterministic, allocation-free)
    zero_deg_k<<<(NNODES + 255) / 256, 256>>>();
    deg_hist_k<<<(NEDGES + 255) / 256, 256>>>(ei);
    scan_k<<<1, 1024>>>();
    fill_csr_k<<<(NEDGES + 255) / 256, 256>>>(ei);

    const int gblk = (NNODES + 63) / 64;

    // layer 1: 128 -> 128, BN1 + leaky   (x -> bufA ; agg -> bufB)
    gemm_scale_k<128, 8><<<gblk, 256>>>(x, 0, 1, W1);
    agg_k<128, true><<<NNODES, 128>>>(1, 2, nullptr, b1, g1, be1, m1, v1);

    // layer 2: 128 -> 128, BN2 + leaky   (bufB -> bufA ; agg -> bufB)
    gemm_scale_k<128, 8><<<gblk, 256>>>(nullptr, 2, 1, W2);
    agg_k<128, true><<<NNODES, 128>>>(1, 2, nullptr, b2, g2, be2, m2, v2);

    // layer 3: 128 -> 64, bias only      (bufB -> bufA ; agg -> out)
    gemm_scale_k<64, 4><<<gblk, 256>>>(nullptr, 2, 1, W3);
    agg_k<64, false><<<(NNODES + 1) / 2, 128>>>(1, 0, out, b3,
                                                nullptr, nullptr, nullptr, nullptr);
}

// round 4
// speedup vs baseline: 1.5526x; 1.5526x over previous
#include <cuda_runtime.h>

#define NNODES 50000
#define NEDGES 800000
#define FIN    128
#define BN_EPS 1e-5f

// ---------------- scratch (device globals: no allocs allowed) ----------------
__device__ float g_bufA[NNODES * 128];
__device__ float g_bufB[NNODES * 128];
__device__ int   g_deg[NNODES];
__device__ int   g_rowptr[NNODES + 1];
__device__ int   g_cursor[NNODES];
__device__ int   g_col[NEDGES];
__device__ float g_dinv[NNODES];

// ---------------- CSR build ----------------
__global__ void zero_deg_k() {
    int i = blockIdx.x * blockDim.x + threadIdx.x;
    if (i < NNODES) g_deg[i] = 0;
}

__global__ void deg_hist_k(const int* __restrict__ ei) {
    int e = blockIdx.x * blockDim.x + threadIdx.x;
    if (e < NEDGES) {
        int dst = ei[NEDGES + e];
        atomicAdd(&g_deg[dst], 1);
    }
}

// warp-shuffle chunked scan over 1024-element chunks
__global__ void scan_k() {
    __shared__ int wsum[32];
    __shared__ int carry;
    int tid = threadIdx.x, lane = tid & 31, wid = tid >> 5;
    if (tid == 0) carry = 0;
    __syncthreads();
    for (int base = 0; base < NNODES; base += 1024) {
        int i = base + tid;
        int v = (i < NNODES) ? g_deg[i] : 0;
        // warp inclusive scan
        int incl = v;
        #pragma unroll
        for (int off = 1; off < 32; off <<= 1) {
            int t = __shfl_up_sync(0xffffffff, incl, off);
            if (lane >= off) incl += t;
        }
        if (lane == 31) wsum[wid] = incl;
        __syncthreads();
        if (wid == 0) {
            int s = wsum[lane];
            #pragma unroll
            for (int off = 1; off < 32; off <<= 1) {
                int t = __shfl_up_sync(0xffffffff, s, off);
                if (lane >= off) s += t;
            }
            wsum[lane] = s;
        }
        __syncthreads();
        int offset = carry + (wid ? wsum[wid - 1] : 0);
        if (i < NNODES) {
            int o = offset + incl - v;   // exclusive
            g_rowptr[i] = o;
            g_cursor[i] = o;
            g_dinv[i]   = rsqrtf(1.0f + (float)v);
        }
        __syncthreads();
        if (tid == 0) carry += wsum[31];
        __syncthreads();
    }
    if (tid == 0) g_rowptr[NNODES] = carry;
}

__global__ void fill_csr_k(const int* __restrict__ ei) {
    int e = blockIdx.x * blockDim.x + threadIdx.x;
    if (e < NEDGES) {
        int src = ei[e];
        int dst = ei[NEDGES + e];
        int pos = atomicAdd(&g_cursor[dst], 1);
        g_col[pos] = src;
    }
}

// ---------------- GEMM: out[row] = (A[row,:] @ W) * dinv[row] ----------------
// BM=128 rows/block, KT=16, 256 threads (16x16), each thread TM=8 x TN=FOUT/16.
template <int FOUT>
__global__ __launch_bounds__(256) void gemm2_k(
    const float* __restrict__ Aext, int selA, int selO,
    const float* __restrict__ W)
{
    const int BM = 128, KT = 16, TM = 8, TN = FOUT / 16;
    __shared__ float As[KT][BM + 4];     // transposed: As[k][row]
    __shared__ float Ws[KT][FOUT];

    const float* A = (selA == 1) ? g_bufA : (selA == 2) ? g_bufB : Aext;
    float* out = (selO == 1) ? g_bufA : g_bufB;

    int tid = threadIdx.x;
    int tx  = tid & 15;      // 0..15 col group
    int ty  = tid >> 4;      // 0..15 row group
    int rb  = blockIdx.x * BM;

    float acc[TM][TN];
    #pragma unroll
    for (int i = 0; i < TM; i++)
        #pragma unroll
        for (int j = 0; j < TN; j++) acc[i][j] = 0.0f;

    for (int kt = 0; kt < FIN; kt += KT) {
        // A tile: 128 rows x 16 k = 512 float4 loads, 2 per thread (transposed store)
        #pragma unroll
        for (int t = 0; t < 2; t++) {
            int idx = tid + t * 256;          // 0..511
            int r = idx >> 2, q = idx & 3;    // row-in-tile, float4-in-k
            int row = rb + r;
            float4 v = make_float4(0.f, 0.f, 0.f, 0.f);
            if (row < NNODES)
                v = *(const float4*)&A[(size_t)row * FIN + kt + q * 4];
            As[q * 4 + 0][r] = v.x;
            As[q * 4 + 1][r] = v.y;
            As[q * 4 + 2][r] = v.z;
            As[q * 4 + 3][r] = v.w;
        }
        // W tile: KT x FOUT floats
        #pragma unroll
        for (int t = 0; t < (KT * FOUT / 4) / 256; t++) {
            int idx = tid + t * 256;
            int k = idx / (FOUT / 4), q = idx % (FOUT / 4);
            *(float4*)&Ws[k][q * 4] = *(const float4*)&W[(size_t)(kt + k) * FOUT + q * 4];
        }
        __syncthreads();

        #pragma unroll
        for (int k = 0; k < KT; k++) {
            float a[TM], w[TN];
            *(float4*)&a[0] = *(float4*)&As[k][ty * TM];
            *(float4*)&a[4] = *(float4*)&As[k][ty * TM + 4];
            #pragma unroll
            for (int j4 = 0; j4 < TN / 4; j4++)
                *(float4*)&w[j4 * 4] = *(float4*)&Ws[k][tx * TN + j4 * 4];
            #pragma unroll
            for (int i = 0; i < TM; i++)
                #pragma unroll
                for (int j = 0; j < TN; j++)
                    acc[i][j] = fmaf(a[i], w[j], acc[i][j]);
        }
        __syncthreads();
    }

    #pragma unroll
    for (int i = 0; i < TM; i++) {
        int row = rb + ty * TM + i;
        if (row < NNODES) {
            float d = g_dinv[row];
            #pragma unroll
            for (int j4 = 0; j4 < TN / 4; j4++) {
                float4 v;
                v.x = acc[i][j4 * 4 + 0] * d;
                v.y = acc[i][j4 * 4 + 1] * d;
                v.z = acc[i][j4 * 4 + 2] * d;
                v.w = acc[i][j4 * 4 + 3] * d;
                *(float4*)&out[(size_t)row * FOUT + tx * TN + j4 * 4] = v;
            }
        }
    }
}

// ---------------- aggregate (warp per dst, float4 lanes, F=128) ----------------
template <bool BNR>
__global__ __launch_bounds__(256) void agg128_k(
    int selH, int selO, float* __restrict__ Oext,
    const float* __restrict__ bias,
    const float* __restrict__ gam, const float* __restrict__ bet,
    const float* __restrict__ mu,  const float* __restrict__ var)
{
    int dst  = blockIdx.x * 8 + (threadIdx.x >> 5);
    int lane = threadIdx.x & 31;
    if (dst >= NNODES) return;

    const float4* hs4 = (selH == 1) ? (const float4*)g_bufA : (const float4*)g_bufB;
    float* outp = Oext ? Oext : ((selO == 1) ? g_bufA : g_bufB);

    int beg = g_rowptr[dst];
    int end = g_rowptr[dst + 1];

    float4 acc = hs4[(size_t)dst * 32 + lane];   // self term (pre-scaled by dinv)
    int e = beg;
    for (; e + 4 <= end; e += 4) {
        int c0 = g_col[e], c1 = g_col[e + 1], c2 = g_col[e + 2], c3 = g_col[e + 3];
        float4 v0 = hs4[(size_t)c0 * 32 + lane];
        float4 v1 = hs4[(size_t)c1 * 32 + lane];
        float4 v2 = hs4[(size_t)c2 * 32 + lane];
        float4 v3 = hs4[(size_t)c3 * 32 + lane];
        acc.x += (v0.x + v1.x) + (v2.x + v3.x);
        acc.y += (v0.y + v1.y) + (v2.y + v3.y);
        acc.z += (v0.z + v1.z) + (v2.z + v3.z);
        acc.w += (v0.w + v1.w) + (v2.w + v3.w);
    }
    for (; e < end; e++) {
        float4 v = hs4[(size_t)g_col[e] * 32 + lane];
        acc.x += v.x; acc.y += v.y; acc.z += v.z; acc.w += v.w;
    }

    float d = g_dinv[dst];
    float4 b4 = ((const float4*)bias)[lane];
    float4 r;
    r.x = acc.x * d + b4.x;
    r.y = acc.y * d + b4.y;
    r.z = acc.z * d + b4.z;
    r.w = acc.w * d + b4.w;
    if (BNR) {
        float4 g4  = ((const float4*)gam)[lane];
        float4 be4 = ((const float4*)bet)[lane];
        float4 m4  = ((const float4*)mu)[lane];
        float4 v4  = ((const float4*)var)[lane];
        r.x = (r.x - m4.x) * rsqrtf(v4.x + BN_EPS) * g4.x + be4.x;
        r.y = (r.y - m4.y) * rsqrtf(v4.y + BN_EPS) * g4.y + be4.y;
        r.z = (r.z - m4.z) * rsqrtf(v4.z + BN_EPS) * g4.z + be4.z;
        r.w = (r.w - m4.w) * rsqrtf(v4.w + BN_EPS) * g4.w + be4.w;
        r.x = r.x > 0.f ? r.x : 0.1f * r.x;
        r.y = r.y > 0.f ? r.y : 0.1f * r.y;
        r.z = r.z > 0.f ? r.z : 0.1f * r.z;
        r.w = r.w > 0.f ? r.w : 0.1f * r.w;
    }
    ((float4*)outp)[(size_t)dst * 32 + lane] = r;
}

// ---------------- aggregate F=64 (warp per dst, float2 lanes, bias only) ------
__global__ __launch_bounds__(256) void agg64_k(
    int selH, float* __restrict__ Oext, const float* __restrict__ bias)
{
    int dst  = blockIdx.x * 8 + (threadIdx.x >> 5);
    int lane = threadIdx.x & 31;
    if (dst >= NNODES) return;

    const float2* hs2 = (selH == 1) ? (const float2*)g_bufA : (const float2*)g_bufB;

    int beg = g_rowptr[dst];
    int end = g_rowptr[dst + 1];

    float2 acc = hs2[(size_t)dst * 32 + lane];
    int e = beg;
    for (; e + 4 <= end; e += 4) {
        int c0 = g_col[e], c1 = g_col[e + 1], c2 = g_col[e + 2], c3 = g_col[e + 3];
        float2 v0 = hs2[(size_t)c0 * 32 + lane];
        float2 v1 = hs2[(size_t)c1 * 32 + lane];
        float2 v2 = hs2[(size_t)c2 * 32 + lane];
        float2 v3 = hs2[(size_t)c3 * 32 + lane];
        acc.x += (v0.x + v1.x) + (v2.x + v3.x);
        acc.y += (v0.y + v1.y) + (v2.y + v3.y);
    }
    for (; e < end; e++) {
        float2 v = hs2[(size_t)g_col[e] * 32 + lane];
        acc.x += v.x; acc.y += v.y;
    }

    float d = g_dinv[dst];
    float2 b2 = ((const float2*)bias)[lane];
    float2 r;
    r.x = acc.x * d + b2.x;
    r.y = acc.y * d + b2.y;
    ((float2*)Oext)[(size_t)dst * 32 + lane] = r;
}

// ---------------- launch ----------------
extern "C" void kernel_launch(void* const* d_in, const int* in_sizes, int n_in,
                              void* d_out, int out_size)
{
    const float* x   = (const float*)d_in[0];
    const int*   ei  = (const int*)d_in[1];
    const float* W1 = (const float*)d_in[2];
    const float* b1 = (const float*)d_in[3];
    const float* g1 = (const float*)d_in[4];
    const float* be1= (const float*)d_in[5];
    const float* m1 = (const float*)d_in[6];
    const float* v1 = (const float*)d_in[7];
    const float* W2 = (const float*)d_in[8];
    const float* b2 = (const float*)d_in[9];
    const float* g2 = (const float*)d_in[10];
    const float* be2= (const float*)d_in[11];
    const float* m2 = (const float*)d_in[12];
    const float* v2 = (const float*)d_in[13];
    const float* W3 = (const float*)d_in[14];
    const float* b3 = (const float*)d_in[15];
    float* out = (float*)d_out;

    // graph structure (rebuilt every call: deterministic, allocation-free)
    zero_deg_k<<<(NNODES + 255) / 256, 256>>>();
    deg_hist_k<<<(NEDGES + 255) / 256, 256>>>(ei);
    scan_k<<<1, 1024>>>();
    fill_csr_k<<<(NEDGES + 255) / 256, 256>>>(ei);

    const int gblk = (NNODES + 127) / 128;
    const int ablk = (NNODES + 7) / 8;

    // layer 1: 128 -> 128, BN1 + leaky   (x -> bufA ; agg -> bufB)
    gemm2_k<128><<<gblk, 256>>>(x, 0, 1, W1);
    agg128_k<true><<<ablk, 256>>>(1, 2, nullptr, b1, g1, be1, m1, v1);

    // layer 2: 128 -> 128, BN2 + leaky   (bufB -> bufA ; agg -> bufB)
    gemm2_k<128><<<gblk, 256>>>(nullptr, 2, 1, W2);
    agg128_k<true><<<ablk, 256>>>(1, 2, nullptr, b2, g2, be2, m2, v2);

    // layer 3: 128 -> 64, bias only      (bufB -> bufA ; agg -> out)
    gemm2_k<64><<<gblk, 256>>>(nullptr, 2, 1, W3);
    agg64_k<<<ablk, 256>>>(1, out, b3);
}

// round 5
// speedup vs baseline: 1.5661x; 1.0087x over previous
#include <cuda_runtime.h>

#define NNODES 50000
#define NEDGES 800000
#define FIN    128
#define BN_EPS 1e-5f

// ---------------- scratch (device globals: no allocs allowed) ----------------
__device__ float g_bufA[NNODES * 128];
__device__ float g_bufB[NNODES * 128];
__device__ int   g_deg[NNODES];
__device__ int   g_rowptr[NNODES + 1];
__device__ int   g_cursor[NNODES];
__device__ int   g_col[NEDGES];
__device__ float g_dinv[NNODES];

// ---------------- CSR build ----------------
__global__ void zero_deg_k() {
    int i = blockIdx.x * blockDim.x + threadIdx.x;
    if (i < NNODES) g_deg[i] = 0;
}

__global__ void deg_hist_k(const int* __restrict__ ei) {
    int e4 = blockIdx.x * blockDim.x + threadIdx.x;
    if (e4 < NEDGES / 4) {
        int4 d = ((const int4*)(ei + NEDGES))[e4];
        atomicAdd(&g_deg[d.x], 1);
        atomicAdd(&g_deg[d.y], 1);
        atomicAdd(&g_deg[d.z], 1);
        atomicAdd(&g_deg[d.w], 1);
    }
}

// warp-shuffle chunked scan over 1024-element chunks
__global__ void scan_k() {
    __shared__ int wsum[32];
    __shared__ int carry;
    int tid = threadIdx.x, lane = tid & 31, wid = tid >> 5;
    if (tid == 0) carry = 0;
    __syncthreads();
    for (int base = 0; base < NNODES; base += 1024) {
        int i = base + tid;
        int v = (i < NNODES) ? g_deg[i] : 0;
        int incl = v;
        #pragma unroll
        for (int off = 1; off < 32; off <<= 1) {
            int t = __shfl_up_sync(0xffffffff, incl, off);
            if (lane >= off) incl += t;
        }
        if (lane == 31) wsum[wid] = incl;
        __syncthreads();
        if (wid == 0) {
            int s = wsum[lane];
            #pragma unroll
            for (int off = 1; off < 32; off <<= 1) {
                int t = __shfl_up_sync(0xffffffff, s, off);
                if (lane >= off) s += t;
            }
            wsum[lane] = s;
        }
        __syncthreads();
        int offset = carry + (wid ? wsum[wid - 1] : 0);
        if (i < NNODES) {
            int o = offset + incl - v;   // exclusive
            g_rowptr[i] = o;
            g_cursor[i] = o;
            g_dinv[i]   = rsqrtf(1.0f + (float)v);
        }
        __syncthreads();
        if (tid == 0) carry += wsum[31];
        __syncthreads();
    }
    if (tid == 0) g_rowptr[NNODES] = carry;
}

__global__ void fill_csr_k(const int* __restrict__ ei) {
    int e4 = blockIdx.x * blockDim.x + threadIdx.x;
    if (e4 < NEDGES / 4) {
        int4 s = ((const int4*)ei)[e4];
        int4 d = ((const int4*)(ei + NEDGES))[e4];
        g_col[atomicAdd(&g_cursor[d.x], 1)] = s.x;
        g_col[atomicAdd(&g_cursor[d.y], 1)] = s.y;
        g_col[atomicAdd(&g_cursor[d.z], 1)] = s.z;
        g_col[atomicAdd(&g_cursor[d.w], 1)] = s.w;
    }
}

// ---------------- tf32 helpers ----------------
__device__ __forceinline__ void split_tf32(float v, unsigned& hi, unsigned& lo) {
    asm("cvt.rna.tf32.f32 %0, %1;" : "=r"(hi) : "f"(v));
    float lf = v - __uint_as_float(hi);
    asm("cvt.rna.tf32.f32 %0, %1;" : "=r"(lo) : "f"(lf));
}

__device__ __forceinline__ void mma_tf32(
    float& c0, float& c1, float& c2, float& c3,
    unsigned a0, unsigned a1, unsigned a2, unsigned a3,
    unsigned b0, unsigned b1)
{
    asm volatile(
        "mma.sync.aligned.m16n8k8.row.col.f32.tf32.tf32.f32 "
        "{%0,%1,%2,%3}, {%4,%5,%6,%7}, {%8,%9}, {%0,%1,%2,%3};"
        : "+f"(c0), "+f"(c1), "+f"(c2), "+f"(c3)
        : "r"(a0), "r"(a1), "r"(a2), "r"(a3), "r"(b0), "r"(b1));
}

// ---------------- tensor GEMM: out[row] = (A[row,:] @ W) * dinv[row] ---------
// BM=128 rows/block, BK=16, 256 threads = 8 warps (MW x NW).
// tf32 split (hi/lo) with 3-term compensation: fp32-class accuracy.
template <int FOUT, int MW, int NW>
__global__ __launch_bounds__(256) void gemm_tc_k(
    const float* __restrict__ Aext, int selA, int selO,
    const float* __restrict__ W)
{
    const int BM = 128, BK = 16;
    const int MT = BM / (16 * MW);      // m16 tiles per warp
    const int NT = FOUT / (8 * NW);     // n8  tiles per warp
    const int APAD = BM + 4;            // stride 132 -> conflict-free frags
    const int WPAD = FOUT + 4;

    __shared__ unsigned As_hi[BK][APAD], As_lo[BK][APAD];
    __shared__ unsigned Ws_hi[BK][WPAD], Ws_lo[BK][WPAD];

    const float* A = (selA == 1) ? g_bufA : (selA == 2) ? g_bufB : Aext;
    float* out = (selO == 1) ? g_bufA : g_bufB;

    int tid  = threadIdx.x;
    int lane = tid & 31;
    int wid  = tid >> 5;
    int warp_m = wid % MW;
    int warp_n = wid / MW;
    int rb = blockIdx.x * BM;

    float c[MT][NT][4];
    #pragma unroll
    for (int mt = 0; mt < MT; mt++)
        #pragma unroll
        for (int nt = 0; nt < NT; nt++)
            #pragma unroll
            for (int q = 0; q < 4; q++) c[mt][nt][q] = 0.0f;

    for (int kt = 0; kt < FIN; kt += BK) {
        // A tile: 128 rows x 16 k, float4 loads -> split -> k-major smem
        #pragma unroll
        for (int t = 0; t < 2; t++) {
            int idx = tid + t * 256;          // 0..511
            int r = idx >> 2, q = idx & 3;
            int row = rb + r;
            float4 v = make_float4(0.f, 0.f, 0.f, 0.f);
            if (row < NNODES)
                v = *(const float4*)&A[(size_t)row * FIN + kt + q * 4];
            unsigned h, l;
            split_tf32(v.x, h, l); As_hi[q * 4 + 0][r] = h; As_lo[q * 4 + 0][r] = l;
            split_tf32(v.y, h, l); As_hi[q * 4 + 1][r] = h; As_lo[q * 4 + 1][r] = l;
            split_tf32(v.z, h, l); As_hi[q * 4 + 2][r] = h; As_lo[q * 4 + 2][r] = l;
            split_tf32(v.w, h, l); As_hi[q * 4 + 3][r] = h; As_lo[q * 4 + 3][r] = l;
        }
        // W tile: 16 x FOUT
        #pragma unroll
        for (int t = 0; t < (BK * FOUT / 4) / 256; t++) {
            int idx = tid + t * 256;
            int k = idx / (FOUT / 4), q = idx % (FOUT / 4);
            float4 v = *(const float4*)&W[(size_t)(kt + k) * FOUT + q * 4];
            unsigned h, l;
            split_tf32(v.x, h, l); Ws_hi[k][q * 4 + 0] = h; Ws_lo[k][q * 4 + 0] = l;
            split_tf32(v.y, h, l); Ws_hi[k][q * 4 + 1] = h; Ws_lo[k][q * 4 + 1] = l;
            split_tf32(v.z, h, l); Ws_hi[k][q * 4 + 2] = h; Ws_lo[k][q * 4 + 2] = l;
            split_tf32(v.w, h, l); Ws_hi[k][q * 4 + 3] = h; Ws_lo[k][q * 4 + 3] = l;
        }
        __syncthreads();

        #pragma unroll
        for (int ks = 0; ks < BK; ks += 8) {
            // A fragments per m-tile
            unsigned ahi[MT][4], alo[MT][4];
            #pragma unroll
            for (int mt = 0; mt < MT; mt++) {
                int mb = warp_m * (MT * 16) + mt * 16;
                int kr = ks + (lane & 3);
                int mc = mb + (lane >> 2);
                ahi[mt][0] = As_hi[kr][mc];     alo[mt][0] = As_lo[kr][mc];
                ahi[mt][1] = As_hi[kr][mc + 8]; alo[mt][1] = As_lo[kr][mc + 8];
                ahi[mt][2] = As_hi[kr + 4][mc];     alo[mt][2] = As_lo[kr + 4][mc];
                ahi[mt][3] = As_hi[kr + 4][mc + 8]; alo[mt][3] = As_lo[kr + 4][mc + 8];
            }
            #pragma unroll
            for (int nt = 0; nt < NT; nt++) {
                int nb = warp_n * (NT * 8) + nt * 8;
                int kr = ks + (lane & 3);
                int nc = nb + (lane >> 2);
                unsigned bh0 = Ws_hi[kr][nc],     bh1 = Ws_hi[kr + 4][nc];
                unsigned bl0 = Ws_lo[kr][nc],     bl1 = Ws_lo[kr + 4][nc];
                #pragma unroll
                for (int mt = 0; mt < MT; mt++) {
                    mma_tf32(c[mt][nt][0], c[mt][nt][1], c[mt][nt][2], c[mt][nt][3],
                             ahi[mt][0], ahi[mt][1], ahi[mt][2], ahi[mt][3], bh0, bh1);
                    mma_tf32(c[mt][nt][0], c[mt][nt][1], c[mt][nt][2], c[mt][nt][3],
                             ahi[mt][0], ahi[mt][1], ahi[mt][2], ahi[mt][3], bl0, bl1);
                    mma_tf32(c[mt][nt][0], c[mt][nt][1], c[mt][nt][2], c[mt][nt][3],
                             alo[mt][0], alo[mt][1], alo[mt][2], alo[mt][3], bh0, bh1);
                }
            }
        }
        __syncthreads();
    }

    // epilogue: scale by dinv[row], store float2 pairs
    #pragma unroll
    for (int mt = 0; mt < MT; mt++) {
        int r0 = rb + warp_m * (MT * 16) + mt * 16 + (lane >> 2);
        int colb = warp_n * (NT * 8) + (lane & 3) * 2;
        if (r0 < NNODES) {
            float d = g_dinv[r0];
            #pragma unroll
            for (int nt = 0; nt < NT; nt++) {
                float2 v = make_float2(c[mt][nt][0] * d, c[mt][nt][1] * d);
                *(float2*)&out[(size_t)r0 * FOUT + colb + nt * 8] = v;
            }
        }
        int r1 = r0 + 8;
        if (r1 < NNODES) {
            float d = g_dinv[r1];
            #pragma unroll
            for (int nt = 0; nt < NT; nt++) {
                float2 v = make_float2(c[mt][nt][2] * d, c[mt][nt][3] * d);
                *(float2*)&out[(size_t)r1 * FOUT + colb + nt * 8] = v;
            }
        }
    }
}

// ---------------- aggregate (warp per dst, float4 lanes, F=128) ----------------
template <bool BNR>
__global__ __launch_bounds__(256) void agg128_k(
    int selH, int selO, float* __restrict__ Oext,
    const float* __restrict__ bias,
    const float* __restrict__ gam, const float* __restrict__ bet,
    const float* __restrict__ mu,  const float* __restrict__ var)
{
    int dst  = blockIdx.x * 8 + (threadIdx.x >> 5);
    int lane = threadIdx.x & 31;
    if (dst >= NNODES) return;

    const float4* hs4 = (selH == 1) ? (const float4*)g_bufA : (const float4*)g_bufB;
    float* outp = Oext ? Oext : ((selO == 1) ? g_bufA : g_bufB);

    int beg = g_rowptr[dst];
    int end = g_rowptr[dst + 1];

    float4 acc = hs4[(size_t)dst * 32 + lane];   // self term (pre-scaled by dinv)
    int e = beg;
    for (; e + 4 <= end; e += 4) {
        int c0 = g_col[e], c1 = g_col[e + 1], c2 = g_col[e + 2], c3 = g_col[e + 3];
        float4 v0 = hs4[(size_t)c0 * 32 + lane];
        float4 v1 = hs4[(size_t)c1 * 32 + lane];
        float4 v2 = hs4[(size_t)c2 * 32 + lane];
        float4 v3 = hs4[(size_t)c3 * 32 + lane];
        acc.x += (v0.x + v1.x) + (v2.x + v3.x);
        acc.y += (v0.y + v1.y) + (v2.y + v3.y);
        acc.z += (v0.z + v1.z) + (v2.z + v3.z);
        acc.w += (v0.w + v1.w) + (v2.w + v3.w);
    }
    for (; e < end; e++) {
        float4 v = hs4[(size_t)g_col[e] * 32 + lane];
        acc.x += v.x; acc.y += v.y; acc.z += v.z; acc.w += v.w;
    }

    float d = g_dinv[dst];
    float4 b4 = ((const float4*)bias)[lane];
    float4 r;
    r.x = acc.x * d + b4.x;
    r.y = acc.y * d + b4.y;
    r.z = acc.z * d + b4.z;
    r.w = acc.w * d + b4.w;
    if (BNR) {
        float4 g4  = ((const float4*)gam)[lane];
        float4 be4 = ((const float4*)bet)[lane];
        float4 m4  = ((const float4*)mu)[lane];
        float4 v4  = ((const float4*)var)[lane];
        r.x = (r.x - m4.x) * rsqrtf(v4.x + BN_EPS) * g4.x + be4.x;
        r.y = (r.y - m4.y) * rsqrtf(v4.y + BN_EPS) * g4.y + be4.y;
        r.z = (r.z - m4.z) * rsqrtf(v4.z + BN_EPS) * g4.z + be4.z;
        r.w = (r.w - m4.w) * rsqrtf(v4.w + BN_EPS) * g4.w + be4.w;
        r.x = r.x > 0.f ? r.x : 0.1f * r.x;
        r.y = r.y > 0.f ? r.y : 0.1f * r.y;
        r.z = r.z > 0.f ? r.z : 0.1f * r.z;
        r.w = r.w > 0.f ? r.w : 0.1f * r.w;
    }
    ((float4*)outp)[(size_t)dst * 32 + lane] = r;
}

// ---------------- aggregate F=64 (warp per dst, float2 lanes, bias only) ------
__global__ __launch_bounds__(256) void agg64_k(
    int selH, float* __restrict__ Oext, const float* __restrict__ bias)
{
    int dst  = blockIdx.x * 8 + (threadIdx.x >> 5);
    int lane = threadIdx.x & 31;
    if (dst >= NNODES) return;

    const float2* hs2 = (selH == 1) ? (const float2*)g_bufA : (const float2*)g_bufB;

    int beg = g_rowptr[dst];
    int end = g_rowptr[dst + 1];

    float2 acc = hs2[(size_t)dst * 32 + lane];
    int e = beg;
    for (; e + 4 <= end; e += 4) {
        int c0 = g_col[e], c1 = g_col[e + 1], c2 = g_col[e + 2], c3 = g_col[e + 3];
        float2 v0 = hs2[(size_t)c0 * 32 + lane];
        float2 v1 = hs2[(size_t)c1 * 32 + lane];
        float2 v2 = hs2[(size_t)c2 * 32 + lane];
        float2 v3 = hs2[(size_t)c3 * 32 + lane];
        acc.x += (v0.x + v1.x) + (v2.x + v3.x);
        acc.y += (v0.y + v1.y) + (v2.y + v3.y);
    }
    for (; e < end; e++) {
        float2 v = hs2[(size_t)g_col[e] * 32 + lane];
        acc.x += v.x; acc.y += v.y;
    }

    float d = g_dinv[dst];
    float2 b2 = ((const float2*)bias)[lane];
    float2 r;
    r.x = acc.x * d + b2.x;
    r.y = acc.y * d + b2.y;
    ((float2*)Oext)[(size_t)dst * 32 + lane] = r;
}

// ---------------- launch ----------------
extern "C" void kernel_launch(void* const* d_in, const int* in_sizes, int n_in,
                              void* d_out, int out_size)
{
    const float* x   = (const float*)d_in[0];
    const int*   ei  = (const int*)d_in[1];
    const float* W1 = (const float*)d_in[2];
    const float* b1 = (const float*)d_in[3];
    const float* g1 = (const float*)d_in[4];
    const float* be1= (const float*)d_in[5];
    const float* m1 = (const float*)d_in[6];
    const float* v1 = (const float*)d_in[7];
    const float* W2 = (const float*)d_in[8];
    const float* b2 = (const float*)d_in[9];
    const float* g2 = (const float*)d_in[10];
    const float* be2= (const float*)d_in[11];
    const float* m2 = (const float*)d_in[12];
    const float* v2 = (const float*)d_in[13];
    const float* W3 = (const float*)d_in[14];
    const float* b3 = (const float*)d_in[15];
    float* out = (float*)d_out;

    // graph structure (rebuilt every call: deterministic, allocation-free)
    zero_deg_k<<<(NNODES + 255) / 256, 256>>>();
    deg_hist_k<<<(NEDGES / 4 + 255) / 256, 256>>>(ei);
    scan_k<<<1, 1024>>>();
    fill_csr_k<<<(NEDGES / 4 + 255) / 256, 256>>>(ei);

    const int gblk = (NNODES + 127) / 128;
    const int ablk = (NNODES + 7) / 8;

    // layer 1: 128 -> 128, BN1 + leaky   (x -> bufA ; agg -> bufB)
    gemm_tc_k<128, 4, 2><<<gblk, 256>>>(x, 0, 1, W1);
    agg128_k<true><<<ablk, 256>>>(1, 2, nullptr, b1, g1, be1, m1, v1);

    // layer 2: 128 -> 128, BN2 + leaky   (bufB -> bufA ; agg -> bufB)
    gemm_tc_k<128, 4, 2><<<gblk, 256>>>(nullptr, 2, 1, W2);
    agg128_k<true><<<ablk, 256>>>(1, 2, nullptr, b2, g2, be2, m2, v2);

    // layer 3: 128 -> 64, bias only      (bufB -> bufA ; agg -> out)
    gemm_tc_k<64, 8, 1><<<gblk, 256>>>(nullptr, 2, 1, W3);
    agg64_k<<<ablk, 256>>>(1, out, b3);
}

// round 6
// speedup vs baseline: 1.6622x; 1.0613x over previous
#include <cuda_runtime.h>
#include <cuda_fp16.h>

#define NNODES 50000
#define NEDGES 800000
#define FIN    128
#define BN_EPS 1e-5f

// ---------------- scratch (device globals: no allocs allowed) ----------------
__device__ float  g_bufA[NNODES * 128];
__device__ float  g_bufB[NNODES * 128];
__device__ __half g_bufH[NNODES * 128];   // fp16 hs for layers 1-2 gathers
__device__ int    g_deg[NNODES];
__device__ int    g_rowptr[NNODES + 1];
__device__ int    g_cursor[NNODES];
__device__ int    g_col[NEDGES];
__device__ float  g_dinv[NNODES];

// ---------------- CSR build ----------------
__global__ void zero_deg_k() {
    int i = blockIdx.x * blockDim.x + threadIdx.x;
    if (i < NNODES) g_deg[i] = 0;
}

__global__ void deg_hist_k(const int* __restrict__ ei) {
    int e4 = blockIdx.x * blockDim.x + threadIdx.x;
    if (e4 < NEDGES / 4) {
        int4 d = ((const int4*)(ei + NEDGES))[e4];
        atomicAdd(&g_deg[d.x], 1);
        atomicAdd(&g_deg[d.y], 1);
        atomicAdd(&g_deg[d.z], 1);
        atomicAdd(&g_deg[d.w], 1);
    }
}

// warp-shuffle chunked scan over 1024-element chunks
__global__ void scan_k() {
    __shared__ int wsum[32];
    __shared__ int carry;
    int tid = threadIdx.x, lane = tid & 31, wid = tid >> 5;
    if (tid == 0) carry = 0;
    __syncthreads();
    for (int base = 0; base < NNODES; base += 1024) {
        int i = base + tid;
        int v = (i < NNODES) ? g_deg[i] : 0;
        int incl = v;
        #pragma unroll
        for (int off = 1; off < 32; off <<= 1) {
            int t = __shfl_up_sync(0xffffffff, incl, off);
            if (lane >= off) incl += t;
        }
        if (lane == 31) wsum[wid] = incl;
        __syncthreads();
        if (wid == 0) {
            int s = wsum[lane];
            #pragma unroll
            for (int off = 1; off < 32; off <<= 1) {
                int t = __shfl_up_sync(0xffffffff, s, off);
                if (lane >= off) s += t;
            }
            wsum[lane] = s;
        }
        __syncthreads();
        int offset = carry + (wid ? wsum[wid - 1] : 0);
        if (i < NNODES) {
            int o = offset + incl - v;   // exclusive
            g_rowptr[i] = o;
            g_cursor[i] = o;
            g_dinv[i]   = rsqrtf(1.0f + (float)v);
        }
        __syncthreads();
        if (tid == 0) carry += wsum[31];
        __syncthreads();
    }
    if (tid == 0) g_rowptr[NNODES] = carry;
}

__global__ void fill_csr_k(const int* __restrict__ ei) {
    int e4 = blockIdx.x * blockDim.x + threadIdx.x;
    if (e4 < NEDGES / 4) {
        int4 s = ((const int4*)ei)[e4];
        int4 d = ((const int4*)(ei + NEDGES))[e4];
        g_col[atomicAdd(&g_cursor[d.x], 1)] = s.x;
        g_col[atomicAdd(&g_cursor[d.y], 1)] = s.y;
        g_col[atomicAdd(&g_cursor[d.z], 1)] = s.z;
        g_col[atomicAdd(&g_cursor[d.w], 1)] = s.w;
    }
}

// ---------------- tf32 helpers ----------------
__device__ __forceinline__ void split_tf32(float v, unsigned& hi, unsigned& lo) {
    asm("cvt.rna.tf32.f32 %0, %1;" : "=r"(hi) : "f"(v));
    float lf = v - __uint_as_float(hi);
    asm("cvt.rna.tf32.f32 %0, %1;" : "=r"(lo) : "f"(lf));
}

__device__ __forceinline__ void mma_tf32(
    float& c0, float& c1, float& c2, float& c3,
    unsigned a0, unsigned a1, unsigned a2, unsigned a3,
    unsigned b0, unsigned b1)
{
    asm volatile(
        "mma.sync.aligned.m16n8k8.row.col.f32.tf32.tf32.f32 "
        "{%0,%1,%2,%3}, {%4,%5,%6,%7}, {%8,%9}, {%0,%1,%2,%3};"
        : "+f"(c0), "+f"(c1), "+f"(c2), "+f"(c3)
        : "r"(a0), "r"(a1), "r"(a2), "r"(a3), "r"(b0), "r"(b1));
}

// ---------------- tensor GEMM: out[row] = (A[row,:] @ W) * dinv[row] ---------
// BM=128 rows/block, BK=16, 256 threads = 8 warps (MW x NW).
// tf32 split (hi/lo), 3-term compensation. H16: write fp16 hs buffer.
template <int FOUT, int MW, int NW, bool H16>
__global__ __launch_bounds__(256) void gemm_tc_k(
    const float* __restrict__ Aext, int selA, int selO,
    const float* __restrict__ W)
{
    const int BM = 128, BK = 16;
    const int MT = BM / (16 * MW);
    const int NT = FOUT / (8 * NW);
    const int APAD = BM + 4;
    const int WPAD = FOUT + 4;

    __shared__ unsigned As_hi[BK][APAD], As_lo[BK][APAD];
    __shared__ unsigned Ws_hi[BK][WPAD], Ws_lo[BK][WPAD];

    const float* A = (selA == 1) ? g_bufA : (selA == 2) ? g_bufB : Aext;
    float* out = (selO == 1) ? g_bufA : g_bufB;

    int tid  = threadIdx.x;
    int lane = tid & 31;
    int wid  = tid >> 5;
    int warp_m = wid % MW;
    int warp_n = wid / MW;
    int rb = blockIdx.x * BM;

    float c[MT][NT][4];
    #pragma unroll
    for (int mt = 0; mt < MT; mt++)
        #pragma unroll
        for (int nt = 0; nt < NT; nt++)
            #pragma unroll
            for (int q = 0; q < 4; q++) c[mt][nt][q] = 0.0f;

    for (int kt = 0; kt < FIN; kt += BK) {
        #pragma unroll
        for (int t = 0; t < 2; t++) {
            int idx = tid + t * 256;
            int r = idx >> 2, q = idx & 3;
            int row = rb + r;
            float4 v = make_float4(0.f, 0.f, 0.f, 0.f);
            if (row < NNODES)
                v = *(const float4*)&A[(size_t)row * FIN + kt + q * 4];
            unsigned h, l;
            split_tf32(v.x, h, l); As_hi[q * 4 + 0][r] = h; As_lo[q * 4 + 0][r] = l;
            split_tf32(v.y, h, l); As_hi[q * 4 + 1][r] = h; As_lo[q * 4 + 1][r] = l;
            split_tf32(v.z, h, l); As_hi[q * 4 + 2][r] = h; As_lo[q * 4 + 2][r] = l;
            split_tf32(v.w, h, l); As_hi[q * 4 + 3][r] = h; As_lo[q * 4 + 3][r] = l;
        }
        #pragma unroll
        for (int t = 0; t < (BK * FOUT / 4) / 256; t++) {
            int idx = tid + t * 256;
            int k = idx / (FOUT / 4), q = idx % (FOUT / 4);
            float4 v = *(const float4*)&W[(size_t)(kt + k) * FOUT + q * 4];
            unsigned h, l;
            split_tf32(v.x, h, l); Ws_hi[k][q * 4 + 0] = h; Ws_lo[k][q * 4 + 0] = l;
            split_tf32(v.y, h, l); Ws_hi[k][q * 4 + 1] = h; Ws_lo[k][q * 4 + 1] = l;
            split_tf32(v.z, h, l); Ws_hi[k][q * 4 + 2] = h; Ws_lo[k][q * 4 + 2] = l;
            split_tf32(v.w, h, l); Ws_hi[k][q * 4 + 3] = h; Ws_lo[k][q * 4 + 3] = l;
        }
        __syncthreads();

        #pragma unroll
        for (int ks = 0; ks < BK; ks += 8) {
            unsigned ahi[MT][4], alo[MT][4];
            #pragma unroll
            for (int mt = 0; mt < MT; mt++) {
                int mb = warp_m * (MT * 16) + mt * 16;
                int kr = ks + (lane & 3);
                int mc = mb + (lane >> 2);
                ahi[mt][0] = As_hi[kr][mc];     alo[mt][0] = As_lo[kr][mc];
                ahi[mt][1] = As_hi[kr][mc + 8]; alo[mt][1] = As_lo[kr][mc + 8];
                ahi[mt][2] = As_hi[kr + 4][mc];     alo[mt][2] = As_lo[kr + 4][mc];
                ahi[mt][3] = As_hi[kr + 4][mc + 8]; alo[mt][3] = As_lo[kr + 4][mc + 8];
            }
            #pragma unroll
            for (int nt = 0; nt < NT; nt++) {
                int nb = warp_n * (NT * 8) + nt * 8;
                int kr = ks + (lane & 3);
                int nc = nb + (lane >> 2);
                unsigned bh0 = Ws_hi[kr][nc],     bh1 = Ws_hi[kr + 4][nc];
                unsigned bl0 = Ws_lo[kr][nc],     bl1 = Ws_lo[kr + 4][nc];
                #pragma unroll
                for (int mt = 0; mt < MT; mt++) {
                    mma_tf32(c[mt][nt][0], c[mt][nt][1], c[mt][nt][2], c[mt][nt][3],
                             ahi[mt][0], ahi[mt][1], ahi[mt][2], ahi[mt][3], bh0, bh1);
                    mma_tf32(c[mt][nt][0], c[mt][nt][1], c[mt][nt][2], c[mt][nt][3],
                             ahi[mt][0], ahi[mt][1], ahi[mt][2], ahi[mt][3], bl0, bl1);
                    mma_tf32(c[mt][nt][0], c[mt][nt][1], c[mt][nt][2], c[mt][nt][3],
                             alo[mt][0], alo[mt][1], alo[mt][2], alo[mt][3], bh0, bh1);
                }
            }
        }
        __syncthreads();
    }

    // epilogue: scale by dinv[row]; store fp32 pairs or fp16 pairs
    #pragma unroll
    for (int mt = 0; mt < MT; mt++) {
        int r0 = rb + warp_m * (MT * 16) + mt * 16 + (lane >> 2);
        int colb = warp_n * (NT * 8) + (lane & 3) * 2;
        #pragma unroll
        for (int half = 0; half < 2; half++) {
            int row = half ? (r0 + 8) : r0;
            int q0 = half * 2;
            if (row < NNODES) {
                float d = g_dinv[row];
                #pragma unroll
                for (int nt = 0; nt < NT; nt++) {
                    float vx = c[mt][nt][q0] * d, vy = c[mt][nt][q0 + 1] * d;
                    if (H16) {
                        *(__half2*)&g_bufH[(size_t)row * FOUT + colb + nt * 8] =
                            __floats2half2_rn(vx, vy);
                    } else {
                        *(float2*)&out[(size_t)row * FOUT + colb + nt * 8] =
                            make_float2(vx, vy);
                    }
                }
            }
        }
    }
}

// ---------------- aggregate fp16 hs (warp per dst, 4 fp16/lane, F=128) --------
// out[dst] = dinv[dst]*(hs[dst] + sum hs[src]) + b, then BN + leaky. fp32 out.
__global__ __launch_bounds__(256) void agg128h_k(
    int selO, const float* __restrict__ bias,
    const float* __restrict__ gam, const float* __restrict__ bet,
    const float* __restrict__ mu,  const float* __restrict__ var)
{
    int dst  = blockIdx.x * 8 + (threadIdx.x >> 5);
    int lane = threadIdx.x & 31;
    if (dst >= NNODES) return;

    const uint2* hs = (const uint2*)g_bufH;   // row = 32 uint2 (4 fp16 each)
    float* outp = (selO == 1) ? g_bufA : g_bufB;

    int beg = g_rowptr[dst];
    int end = g_rowptr[dst + 1];

    float4 acc;
    {
        uint2 v = hs[(size_t)dst * 32 + lane];
        float2 f0 = __half22float2(*(__half2*)&v.x);
        float2 f1 = __half22float2(*(__half2*)&v.y);
        acc = make_float4(f0.x, f0.y, f1.x, f1.y);
    }

    int e = beg;
    for (; e + 8 <= end; e += 8) {
        uint2 v[8];
        #pragma unroll
        for (int u = 0; u < 8; u++)
            v[u] = hs[(size_t)g_col[e + u] * 32 + lane];
        #pragma unroll
        for (int u = 0; u < 8; u++) {
            float2 f0 = __half22float2(*(__half2*)&v[u].x);
            float2 f1 = __half22float2(*(__half2*)&v[u].y);
            acc.x += f0.x; acc.y += f0.y; acc.z += f1.x; acc.w += f1.y;
        }
    }
    for (; e < end; e++) {
        uint2 v = hs[(size_t)g_col[e] * 32 + lane];
        float2 f0 = __half22float2(*(__half2*)&v.x);
        float2 f1 = __half22float2(*(__half2*)&v.y);
        acc.x += f0.x; acc.y += f0.y; acc.z += f1.x; acc.w += f1.y;
    }

    float d = g_dinv[dst];
    float4 b4 = ((const float4*)bias)[lane];
    float4 r;
    r.x = acc.x * d + b4.x;
    r.y = acc.y * d + b4.y;
    r.z = acc.z * d + b4.z;
    r.w = acc.w * d + b4.w;
    float4 g4  = ((const float4*)gam)[lane];
    float4 be4 = ((const float4*)bet)[lane];
    float4 m4  = ((const float4*)mu)[lane];
    float4 v4  = ((const float4*)var)[lane];
    r.x = (r.x - m4.x) * rsqrtf(v4.x + BN_EPS) * g4.x + be4.x;
    r.y = (r.y - m4.y) * rsqrtf(v4.y + BN_EPS) * g4.y + be4.y;
    r.z = (r.z - m4.z) * rsqrtf(v4.z + BN_EPS) * g4.z + be4.z;
    r.w = (r.w - m4.w) * rsqrtf(v4.w + BN_EPS) * g4.w + be4.w;
    r.x = r.x > 0.f ? r.x : 0.1f * r.x;
    r.y = r.y > 0.f ? r.y : 0.1f * r.y;
    r.z = r.z > 0.f ? r.z : 0.1f * r.z;
    r.w = r.w > 0.f ? r.w : 0.1f * r.w;
    ((float4*)outp)[(size_t)dst * 32 + lane] = r;
}

// ---------------- aggregate F=64 fp32 (warp per dst, float2 lanes) ------------
__global__ __launch_bounds__(256) void agg64_k(
    int selH, float* __restrict__ Oext, const float* __restrict__ bias)
{
    int dst  = blockIdx.x * 8 + (threadIdx.x >> 5);
    int lane = threadIdx.x & 31;
    if (dst >= NNODES) return;

    const float2* hs2 = (selH == 1) ? (const float2*)g_bufA : (const float2*)g_bufB;

    int beg = g_rowptr[dst];
    int end = g_rowptr[dst + 1];

    float2 acc = hs2[(size_t)dst * 32 + lane];
    int e = beg;
    for (; e + 8 <= end; e += 8) {
        float2 v[8];
        #pragma unroll
        for (int u = 0; u < 8; u++)
            v[u] = hs2[(size_t)g_col[e + u] * 32 + lane];
        #pragma unroll
        for (int u = 0; u < 8; u++) { acc.x += v[u].x; acc.y += v[u].y; }
    }
    for (; e < end; e++) {
        float2 v = hs2[(size_t)g_col[e] * 32 + lane];
        acc.x += v.x; acc.y += v.y;
    }

    float d = g_dinv[dst];
    float2 b2 = ((const float2*)bias)[lane];
    float2 r;
    r.x = acc.x * d + b2.x;
    r.y = acc.y * d + b2.y;
    ((float2*)Oext)[(size_t)dst * 32 + lane] = r;
}

// ---------------- launch ----------------
extern "C" void kernel_launch(void* const* d_in, const int* in_sizes, int n_in,
                              void* d_out, int out_size)
{
    const float* x   = (const float*)d_in[0];
    const int*   ei  = (const int*)d_in[1];
    const float* W1 = (const float*)d_in[2];
    const float* b1 = (const float*)d_in[3];
    const float* g1 = (const float*)d_in[4];
    const float* be1= (const float*)d_in[5];
    const float* m1 = (const float*)d_in[6];
    const float* v1 = (const float*)d_in[7];
    const float* W2 = (const float*)d_in[8];
    const float* b2 = (const float*)d_in[9];
    const float* g2 = (const float*)d_in[10];
    const float* be2= (const float*)d_in[11];
    const float* m2 = (const float*)d_in[12];
    const float* v2 = (const float*)d_in[13];
    const float* W3 = (const float*)d_in[14];
    const float* b3 = (const float*)d_in[15];
    float* out = (float*)d_out;

    // graph structure (rebuilt every call: deterministic, allocation-free)
    zero_deg_k<<<(NNODES + 255) / 256, 256>>>();
    deg_hist_k<<<(NEDGES / 4 + 255) / 256, 256>>>(ei);
    scan_k<<<1, 1024>>>();
    fill_csr_k<<<(NEDGES / 4 + 255) / 256, 256>>>(ei);

    const int gblk = (NNODES + 127) / 128;
    const int ablk = (NNODES + 7) / 8;

    // layer 1: 128 -> 128, BN1 + leaky   (x -> H fp16 ; agg -> bufB fp32)
    gemm_tc_k<128, 4, 2, true><<<gblk, 256>>>(x, 0, 2, W1);
    agg128h_k<<<ablk, 256>>>(2, b1, g1, be1, m1, v1);

    // layer 2: 128 -> 128, BN2 + leaky   (bufB -> H fp16 ; agg -> bufB fp32)
    gemm_tc_k<128, 4, 2, true><<<gblk, 256>>>(nullptr, 2, 2, W2);
    agg128h_k<<<ablk, 256>>>(2, b2, g2, be2, m2, v2);

    // layer 3: 128 -> 64, bias only      (bufB -> bufA fp32 ; agg -> out)
    gemm_tc_k<64, 8, 1, false><<<gblk, 256>>>(nullptr, 2, 1, W3);
    agg64_k<<<ablk, 256>>>(1, out, b3);
}

// round 7
// speedup vs baseline: 1.9635x; 1.1813x over previous
#include <cuda_runtime.h>
#include <cuda_fp16.h>

#define NNODES 50000
#define NEDGES 800000
#define FIN    128
#define BN_EPS 1e-5f
#define NCHUNK ((NNODES + 1023) / 1024)   // 49

// ---------------- scratch (device globals: no allocs allowed) ----------------
__device__ float  g_bufA[NNODES * 128];
__device__ float  g_bufB[NNODES * 128];
__device__ __half g_bufH[NNODES * 128];   // fp16 hs for layers 1-2 gathers
__device__ int    g_deg[NNODES];
__device__ int    g_rowptr[NNODES + 1];
__device__ int    g_cursor[NNODES];
__device__ int    g_col[NEDGES];
__device__ float  g_dinv[NNODES];
__device__ int    g_bsum[NCHUNK];
__device__ int    g_boff[NCHUNK];

// ---------------- CSR build ----------------
__global__ void zero_deg_k() {
    int i = blockIdx.x * blockDim.x + threadIdx.x;
    if (i < NNODES) g_deg[i] = 0;
}

__global__ void deg_hist_k(const int* __restrict__ ei) {
    int e4 = blockIdx.x * blockDim.x + threadIdx.x;
    if (e4 < NEDGES / 4) {
        int4 d = ((const int4*)(ei + NEDGES))[e4];
        atomicAdd(&g_deg[d.x], 1);
        atomicAdd(&g_deg[d.y], 1);
        atomicAdd(&g_deg[d.z], 1);
        atomicAdd(&g_deg[d.w], 1);
    }
}

// block sums of 1024-element chunks
__global__ void scan1_k() {
    __shared__ int ws[8];
    int b = blockIdx.x, tid = threadIdx.x, lane = tid & 31, wid = tid >> 5;
    int base = b * 1024 + tid * 4;
    int s = 0;
    #pragma unroll
    for (int u = 0; u < 4; u++) {
        int i = base + u;
        if (i < NNODES) s += g_deg[i];
    }
    #pragma unroll
    for (int off = 16; off > 0; off >>= 1)
        s += __shfl_down_sync(0xffffffff, s, off);
    if (lane == 0) ws[wid] = s;
    __syncthreads();
    if (tid == 0) {
        int t = 0;
        #pragma unroll
        for (int w = 0; w < 8; w++) t += ws[w];
        g_bsum[b] = t;
    }
}

// exclusive scan of NCHUNK block sums (single block, 64 threads)
__global__ void scan2_k() {
    __shared__ int s[64];
    int tid = threadIdx.x;
    s[tid] = (tid < NCHUNK) ? g_bsum[tid] : 0;
    __syncthreads();
    #pragma unroll
    for (int off = 1; off < 64; off <<= 1) {
        int t = (tid >= off) ? s[tid - off] : 0;
        __syncthreads();
        s[tid] += t;
        __syncthreads();
    }
    if (tid < NCHUNK) g_boff[tid] = s[tid] - g_bsum[tid];   // exclusive
    if (tid == 0) g_rowptr[NNODES] = NEDGES;
}

// per-chunk scan + write rowptr/cursor/dinv
__global__ void scan3_k() {
    __shared__ int wsum[32];
    int b = blockIdx.x, tid = threadIdx.x, lane = tid & 31, wid = tid >> 5;
    int i = b * 1024 + tid;
    int v = (i < NNODES) ? g_deg[i] : 0;
    int incl = v;
    #pragma unroll
    for (int off = 1; off < 32; off <<= 1) {
        int t = __shfl_up_sync(0xffffffff, incl, off);
        if (lane >= off) incl += t;
    }
    if (lane == 31) wsum[wid] = incl;
    __syncthreads();
    if (wid == 0) {
        int s = (lane < 32) ? wsum[lane] : 0;
        #pragma unroll
        for (int off = 1; off < 32; off <<= 1) {
            int t = __shfl_up_sync(0xffffffff, s, off);
            if (lane >= off) s += t;
        }
        wsum[lane] = s;
    }
    __syncthreads();
    if (i < NNODES) {
        int o = g_boff[b] + (wid ? wsum[wid - 1] : 0) + incl - v;  // exclusive
        g_rowptr[i] = o;
        g_cursor[i] = o;
        g_dinv[i]   = rsqrtf(1.0f + (float)v);
    }
}

__global__ void fill_csr_k(const int* __restrict__ ei) {
    int e4 = blockIdx.x * blockDim.x + threadIdx.x;
    if (e4 < NEDGES / 4) {
        int4 s = ((const int4*)ei)[e4];
        int4 d = ((const int4*)(ei + NEDGES))[e4];
        g_col[atomicAdd(&g_cursor[d.x], 1)] = s.x;
        g_col[atomicAdd(&g_cursor[d.y], 1)] = s.y;
        g_col[atomicAdd(&g_cursor[d.z], 1)] = s.z;
        g_col[atomicAdd(&g_cursor[d.w], 1)] = s.w;
    }
}

// ---------------- tf32 helpers ----------------
__device__ __forceinline__ void split_tf32(float v, unsigned& hi, unsigned& lo) {
    asm("cvt.rna.tf32.f32 %0, %1;" : "=r"(hi) : "f"(v));
    float lf = v - __uint_as_float(hi);
    asm("cvt.rna.tf32.f32 %0, %1;" : "=r"(lo) : "f"(lf));
}

__device__ __forceinline__ void mma_tf32(
    float& c0, float& c1, float& c2, float& c3,
    unsigned a0, unsigned a1, unsigned a2, unsigned a3,
    unsigned b0, unsigned b1)
{
    asm volatile(
        "mma.sync.aligned.m16n8k8.row.col.f32.tf32.tf32.f32 "
        "{%0,%1,%2,%3}, {%4,%5,%6,%7}, {%8,%9}, {%0,%1,%2,%3};"
        : "+f"(c0), "+f"(c1), "+f"(c2), "+f"(c3)
        : "r"(a0), "r"(a1), "r"(a2), "r"(a3), "r"(b0), "r"(b1));
}

// ---------------- tensor GEMM: out[row] = (A[row,:] @ W) [* dinv[row]] -------
// BM=128, BK=16, 256 threads = 8 warps (MW x NW). tf32 hi/lo, 3-term comp.
template <int FOUT, int MW, int NW, bool H16, bool SCALE>
__global__ __launch_bounds__(256) void gemm_tc_k(
    const float* __restrict__ Aext, int selA, int selO,
    const float* __restrict__ W)
{
    const int BM = 128, BK = 16;
    const int MT = BM / (16 * MW);
    const int NT = FOUT / (8 * NW);
    const int APAD = BM + 4;
    const int WPAD = FOUT + 4;

    __shared__ unsigned As_hi[BK][APAD], As_lo[BK][APAD];
    __shared__ unsigned Ws_hi[BK][WPAD], Ws_lo[BK][WPAD];

    const float* A = (selA == 1) ? g_bufA : (selA == 2) ? g_bufB : Aext;
    float* out = (selO == 1) ? g_bufA : g_bufB;

    int tid  = threadIdx.x;
    int lane = tid & 31;
    int wid  = tid >> 5;
    int warp_m = wid % MW;
    int warp_n = wid / MW;
    int rb = blockIdx.x * BM;

    float c[MT][NT][4];
    #pragma unroll
    for (int mt = 0; mt < MT; mt++)
        #pragma unroll
        for (int nt = 0; nt < NT; nt++)
            #pragma unroll
            for (int q = 0; q < 4; q++) c[mt][nt][q] = 0.0f;

    for (int kt = 0; kt < FIN; kt += BK) {
        #pragma unroll
        for (int t = 0; t < 2; t++) {
            int idx = tid + t * 256;
            int r = idx >> 2, q = idx & 3;
            int row = rb + r;
            float4 v = make_float4(0.f, 0.f, 0.f, 0.f);
            if (row < NNODES)
                v = *(const float4*)&A[(size_t)row * FIN + kt + q * 4];
            unsigned h, l;
            split_tf32(v.x, h, l); As_hi[q * 4 + 0][r] = h; As_lo[q * 4 + 0][r] = l;
            split_tf32(v.y, h, l); As_hi[q * 4 + 1][r] = h; As_lo[q * 4 + 1][r] = l;
            split_tf32(v.z, h, l); As_hi[q * 4 + 2][r] = h; As_lo[q * 4 + 2][r] = l;
            split_tf32(v.w, h, l); As_hi[q * 4 + 3][r] = h; As_lo[q * 4 + 3][r] = l;
        }
        #pragma unroll
        for (int t = 0; t < (BK * FOUT / 4) / 256; t++) {
            int idx = tid + t * 256;
            int k = idx / (FOUT / 4), q = idx % (FOUT / 4);
            float4 v = *(const float4*)&W[(size_t)(kt + k) * FOUT + q * 4];
            unsigned h, l;
            split_tf32(v.x, h, l); Ws_hi[k][q * 4 + 0] = h; Ws_lo[k][q * 4 + 0] = l;
            split_tf32(v.y, h, l); Ws_hi[k][q * 4 + 1] = h; Ws_lo[k][q * 4 + 1] = l;
            split_tf32(v.z, h, l); Ws_hi[k][q * 4 + 2] = h; Ws_lo[k][q * 4 + 2] = l;
            split_tf32(v.w, h, l); Ws_hi[k][q * 4 + 3] = h; Ws_lo[k][q * 4 + 3] = l;
        }
        __syncthreads();

        #pragma unroll
        for (int ks = 0; ks < BK; ks += 8) {
            unsigned ahi[MT][4], alo[MT][4];
            #pragma unroll
            for (int mt = 0; mt < MT; mt++) {
                int mb = warp_m * (MT * 16) + mt * 16;
                int kr = ks + (lane & 3);
                int mc = mb + (lane >> 2);
                ahi[mt][0] = As_hi[kr][mc];     alo[mt][0] = As_lo[kr][mc];
                ahi[mt][1] = As_hi[kr][mc + 8]; alo[mt][1] = As_lo[kr][mc + 8];
                ahi[mt][2] = As_hi[kr + 4][mc];     alo[mt][2] = As_lo[kr + 4][mc];
                ahi[mt][3] = As_hi[kr + 4][mc + 8]; alo[mt][3] = As_lo[kr + 4][mc + 8];
            }
            #pragma unroll
            for (int nt = 0; nt < NT; nt++) {
                int nb = warp_n * (NT * 8) + nt * 8;
                int kr = ks + (lane & 3);
                int nc = nb + (lane >> 2);
                unsigned bh0 = Ws_hi[kr][nc],     bh1 = Ws_hi[kr + 4][nc];
                unsigned bl0 = Ws_lo[kr][nc],     bl1 = Ws_lo[kr + 4][nc];
                #pragma unroll
                for (int mt = 0; mt < MT; mt++) {
                    mma_tf32(c[mt][nt][0], c[mt][nt][1], c[mt][nt][2], c[mt][nt][3],
                             ahi[mt][0], ahi[mt][1], ahi[mt][2], ahi[mt][3], bh0, bh1);
                    mma_tf32(c[mt][nt][0], c[mt][nt][1], c[mt][nt][2], c[mt][nt][3],
                             ahi[mt][0], ahi[mt][1], ahi[mt][2], ahi[mt][3], bl0, bl1);
                    mma_tf32(c[mt][nt][0], c[mt][nt][1], c[mt][nt][2], c[mt][nt][3],
                             alo[mt][0], alo[mt][1], alo[mt][2], alo[mt][3], bh0, bh1);
                }
            }
        }
        __syncthreads();
    }

    #pragma unroll
    for (int mt = 0; mt < MT; mt++) {
        int r0 = rb + warp_m * (MT * 16) + mt * 16 + (lane >> 2);
        int colb = warp_n * (NT * 8) + (lane & 3) * 2;
        #pragma unroll
        for (int half = 0; half < 2; half++) {
            int row = half ? (r0 + 8) : r0;
            int q0 = half * 2;
            if (row < NNODES) {
                float d = SCALE ? g_dinv[row] : 1.0f;
                #pragma unroll
                for (int nt = 0; nt < NT; nt++) {
                    float vx = c[mt][nt][q0] * d, vy = c[mt][nt][q0 + 1] * d;
                    if (H16) {
                        *(__half2*)&g_bufH[(size_t)row * FOUT + colb + nt * 8] =
                            __floats2half2_rn(vx, vy);
                    } else {
                        *(float2*)&out[(size_t)row * FOUT + colb + nt * 8] =
                            make_float2(vx, vy);
                    }
                }
            }
        }
    }
}

// ---------------- aggregate fp16 hs (half-warp per dst, uint4/lane, F=128) ----
// SRCSCALE: hs holds unscaled h; multiply dinv[src] per edge (layer 1).
template <bool SRCSCALE>
__global__ __launch_bounds__(256) void agg128h_k(
    int selO, const float* __restrict__ bias,
    const float* __restrict__ gam, const float* __restrict__ bet,
    const float* __restrict__ mu,  const float* __restrict__ var)
{
    int dst  = blockIdx.x * 16 + (threadIdx.x >> 4);
    int lane = threadIdx.x & 15;
    if (dst >= NNODES) return;

    const uint4* hs = (const uint4*)g_bufH;   // row = 16 uint4 (8 fp16 each)
    float* outp = (selO == 1) ? g_bufA : g_bufB;

    int beg = g_rowptr[dst];
    int end = g_rowptr[dst + 1];
    float d = g_dinv[dst];

    float acc[8];
    {
        uint4 v = hs[(size_t)dst * 16 + lane];
        float2 f0 = __half22float2(*(__half2*)&v.x);
        float2 f1 = __half22float2(*(__half2*)&v.y);
        float2 f2 = __half22float2(*(__half2*)&v.z);
        float2 f3 = __half22float2(*(__half2*)&v.w);
        float sd = SRCSCALE ? d : 1.0f;
        acc[0] = f0.x * sd; acc[1] = f0.y * sd;
        acc[2] = f1.x * sd; acc[3] = f1.y * sd;
        acc[4] = f2.x * sd; acc[5] = f2.y * sd;
        acc[6] = f3.x * sd; acc[7] = f3.y * sd;
    }

    int e = beg;
    for (; e + 8 <= end; e += 8) {
        uint4 v[8]; float sc[8];
        #pragma unroll
        for (int u = 0; u < 8; u++) {
            int c = g_col[e + u];
            v[u] = hs[(size_t)c * 16 + lane];
            sc[u] = SRCSCALE ? g_dinv[c] : 1.0f;
        }
        #pragma unroll
        for (int u = 0; u < 8; u++) {
            float2 f0 = __half22float2(*(__half2*)&v[u].x);
            float2 f1 = __half22float2(*(__half2*)&v[u].y);
            float2 f2 = __half22float2(*(__half2*)&v[u].z);
            float2 f3 = __half22float2(*(__half2*)&v[u].w);
            acc[0] += f0.x * sc[u]; acc[1] += f0.y * sc[u];
            acc[2] += f1.x * sc[u]; acc[3] += f1.y * sc[u];
            acc[4] += f2.x * sc[u]; acc[5] += f2.y * sc[u];
            acc[6] += f3.x * sc[u]; acc[7] += f3.y * sc[u];
        }
    }
    for (; e < end; e++) {
        int c = g_col[e];
        uint4 v = hs[(size_t)c * 16 + lane];
        float sc = SRCSCALE ? g_dinv[c] : 1.0f;
        float2 f0 = __half22float2(*(__half2*)&v.x);
        float2 f1 = __half22float2(*(__half2*)&v.y);
        float2 f2 = __half22float2(*(__half2*)&v.z);
        float2 f3 = __half22float2(*(__half2*)&v.w);
        acc[0] += f0.x * sc; acc[1] += f0.y * sc;
        acc[2] += f1.x * sc; acc[3] += f1.y * sc;
        acc[4] += f2.x * sc; acc[5] += f2.y * sc;
        acc[6] += f3.x * sc; acc[7] += f3.y * sc;
    }

    float4 b0 = ((const float4*)bias)[lane * 2],     b1 = ((const float4*)bias)[lane * 2 + 1];
    float4 g0 = ((const float4*)gam)[lane * 2],      g1 = ((const float4*)gam)[lane * 2 + 1];
    float4 t0 = ((const float4*)bet)[lane * 2],      t1 = ((const float4*)bet)[lane * 2 + 1];
    float4 m0 = ((const float4*)mu)[lane * 2],       m1 = ((const float4*)mu)[lane * 2 + 1];
    float4 v0 = ((const float4*)var)[lane * 2],      v1 = ((const float4*)var)[lane * 2 + 1];
    float bb[8] = {b0.x, b0.y, b0.z, b0.w, b1.x, b1.y, b1.z, b1.w};
    float gg[8] = {g0.x, g0.y, g0.z, g0.w, g1.x, g1.y, g1.z, g1.w};
    float tt[8] = {t0.x, t0.y, t0.z, t0.w, t1.x, t1.y, t1.z, t1.w};
    float mm[8] = {m0.x, m0.y, m0.z, m0.w, m1.x, m1.y, m1.z, m1.w};
    float vv[8] = {v0.x, v0.y, v0.z, v0.w, v1.x, v1.y, v1.z, v1.w};

    float r[8];
    #pragma unroll
    for (int q = 0; q < 8; q++) {
        float val = acc[q] * d + bb[q];
        val = (val - mm[q]) * rsqrtf(vv[q] + BN_EPS) * gg[q] + tt[q];
        r[q] = val > 0.f ? val : 0.1f * val;
    }
    float4* orow = (float4*)&outp[(size_t)dst * 128 + lane * 8];
    orow[0] = make_float4(r[0], r[1], r[2], r[3]);
    orow[1] = make_float4(r[4], r[5], r[6], r[7]);
}

// ---------------- aggregate F=64 fp32 (half-warp per dst, float4/lane) --------
__global__ __launch_bounds__(256) void agg64_k(
    int selH, float* __restrict__ Oext, const float* __restrict__ bias)
{
    int dst  = blockIdx.x * 16 + (threadIdx.x >> 4);
    int lane = threadIdx.x & 15;
    if (dst >= NNODES) return;

    const float4* hs = (selH == 1) ? (const float4*)g_bufA : (const float4*)g_bufB;

    int beg = g_rowptr[dst];
    int end = g_rowptr[dst + 1];

    float4 acc = hs[(size_t)dst * 16 + lane];
    int e = beg;
    for (; e + 8 <= end; e += 8) {
        float4 v[8];
        #pragma unroll
        for (int u = 0; u < 8; u++)
            v[u] = hs[(size_t)g_col[e + u] * 16 + lane];
        #pragma unroll
        for (int u = 0; u < 8; u++) {
            acc.x += v[u].x; acc.y += v[u].y; acc.z += v[u].z; acc.w += v[u].w;
        }
    }
    for (; e < end; e++) {
        float4 v = hs[(size_t)g_col[e] * 16 + lane];
        acc.x += v.x; acc.y += v.y; acc.z += v.z; acc.w += v.w;
    }

    float d = g_dinv[dst];
    float4 b4 = ((const float4*)bias)[lane];
    float4 r;
    r.x = acc.x * d + b4.x;
    r.y = acc.y * d + b4.y;
    r.z = acc.z * d + b4.z;
    r.w = acc.w * d + b4.w;
    ((float4*)Oext)[(size_t)dst * 16 + lane] = r;
}

// ---------------- launch ----------------
extern "C" void kernel_launch(void* const* d_in, const int* in_sizes, int n_in,
                              void* d_out, int out_size)
{
    const float* x   = (const float*)d_in[0];
    const int*   ei  = (const int*)d_in[1];
    const float* W1 = (const float*)d_in[2];
    const float* b1 = (const float*)d_in[3];
    const float* g1 = (const float*)d_in[4];
    const float* be1= (const float*)d_in[5];
    const float* m1 = (const float*)d_in[6];
    const float* v1 = (const float*)d_in[7];
    const float* W2 = (const float*)d_in[8];
    const float* b2 = (const float*)d_in[9];
    const float* g2 = (const float*)d_in[10];
    const float* be2= (const float*)d_in[11];
    const float* m2 = (const float*)d_in[12];
    const float* v2 = (const float*)d_in[13];
    const float* W3 = (const float*)d_in[14];
    const float* b3 = (const float*)d_in[15];
    float* out = (float*)d_out;

    // side stream + events, created once on the (non-captured) correctness call
    static cudaStream_t s2 = nullptr;
    static cudaEvent_t evF = nullptr, evJ = nullptr;
    if (s2 == nullptr) {
        cudaStreamCreateWithFlags(&s2, cudaStreamNonBlocking);
        cudaEventCreateWithFlags(&evF, cudaEventDisableTiming);
        cudaEventCreateWithFlags(&evJ, cudaEventDisableTiming);
    }

    const int gblk = (NNODES + 127) / 128;
    const int ablk = (NNODES + 15) / 16;

    // fork: CSR build on s2, concurrent with GEMM1 (which no longer needs dinv)
    cudaEventRecord(evF, 0);
    cudaStreamWaitEvent(s2, evF, 0);
    zero_deg_k<<<(NNODES + 255) / 256, 256, 0, s2>>>();
    deg_hist_k<<<(NEDGES / 4 + 255) / 256, 256, 0, s2>>>(ei);
    scan1_k<<<NCHUNK, 256, 0, s2>>>();
    scan2_k<<<1, 64, 0, s2>>>();
    scan3_k<<<NCHUNK, 1024, 0, s2>>>();
    fill_csr_k<<<(NEDGES / 4 + 255) / 256, 256, 0, s2>>>(ei);

    // layer 1 GEMM: x @ W1 -> H fp16 (unscaled)
    gemm_tc_k<128, 4, 2, true, false><<<gblk, 256>>>(x, 0, 2, W1);

    // join
    cudaEventRecord(evJ, s2);
    cudaStreamWaitEvent(0, evJ, 0);

    // layer 1 agg (applies dinv[src] inline), BN1 + leaky -> bufB fp32
    agg128h_k<true><<<ablk, 256>>>(2, b1, g1, be1, m1, v1);

    // layer 2: 128 -> 128, BN2 + leaky   (bufB -> H fp16 scaled ; agg -> bufB)
    gemm_tc_k<128, 4, 2, true, true><<<gblk, 256>>>(nullptr, 2, 2, W2);
    agg128h_k<false><<<ablk, 256>>>(2, b2, g2, be2, m2, v2);

    // layer 3: 128 -> 64, bias only      (bufB -> bufA fp32 scaled ; agg -> out)
    gemm_tc_k<64, 8, 1, false, true><<<gblk, 256>>>(nullptr, 2, 1, W3);
    agg64_k<<<ablk, 256>>>(1, out, b3);
}

// round 8
// speedup vs baseline: 2.7727x; 1.4121x over previous
#include <cuda_runtime.h>
#include <cuda_fp16.h>
#include <cuda_bf16.h>

#define NNODES 50000
#define NEDGES 800000
#define FIN    128
#define BN_EPS 1e-5f
#define NCHUNK ((NNODES + 1023) / 1024)   // 49

// ---------------- scratch (device globals: no allocs allowed) ----------------
__device__ float  g_bufA[NNODES * 128];
__device__ float  g_bufB[NNODES * 128];
__device__ __half g_bufH[NNODES * 128];   // fp16 hs for gathers
__device__ int    g_deg[NNODES];
__device__ int    g_rowptr[NNODES + 1];
__device__ int    g_cursor[NNODES];
__device__ int    g_col[NEDGES];
__device__ float  g_dinv[NNODES];
__device__ int    g_bsum[NCHUNK];
__device__ int    g_boff[NCHUNK];

// ---------------- CSR build ----------------
__global__ void zero_deg_k() {
    int i = blockIdx.x * blockDim.x + threadIdx.x;
    if (i < NNODES) g_deg[i] = 0;
}

__global__ void deg_hist_k(const int* __restrict__ ei) {
    int e4 = blockIdx.x * blockDim.x + threadIdx.x;
    if (e4 < NEDGES / 4) {
        int4 d = ((const int4*)(ei + NEDGES))[e4];
        atomicAdd(&g_deg[d.x], 1);
        atomicAdd(&g_deg[d.y], 1);
        atomicAdd(&g_deg[d.z], 1);
        atomicAdd(&g_deg[d.w], 1);
    }
}

// block sums of 1024-element chunks
__global__ void scan1_k() {
    __shared__ int ws[8];
    int b = blockIdx.x, tid = threadIdx.x, lane = tid & 31, wid = tid >> 5;
    int base = b * 1024 + tid * 4;
    int s = 0;
    #pragma unroll
    for (int u = 0; u < 4; u++) {
        int i = base + u;
        if (i < NNODES) s += g_deg[i];
    }
    #pragma unroll
    for (int off = 16; off > 0; off >>= 1)
        s += __shfl_down_sync(0xffffffff, s, off);
    if (lane == 0) ws[wid] = s;
    __syncthreads();
    if (tid == 0) {
        int t = 0;
        #pragma unroll
        for (int w = 0; w < 8; w++) t += ws[w];
        g_bsum[b] = t;
    }
}

// exclusive scan of NCHUNK block sums (single block, 64 threads)
__global__ void scan2_k() {
    __shared__ int s[64];
    int tid = threadIdx.x;
    s[tid] = (tid < NCHUNK) ? g_bsum[tid] : 0;
    __syncthreads();
    #pragma unroll
    for (int off = 1; off < 64; off <<= 1) {
        int t = (tid >= off) ? s[tid - off] : 0;
        __syncthreads();
        s[tid] += t;
        __syncthreads();
    }
    if (tid < NCHUNK) g_boff[tid] = s[tid] - g_bsum[tid];   // exclusive
    if (tid == 0) g_rowptr[NNODES] = NEDGES;
}

// per-chunk scan + write rowptr/cursor/dinv
__global__ void scan3_k() {
    __shared__ int wsum[32];
    int b = blockIdx.x, tid = threadIdx.x, lane = tid & 31, wid = tid >> 5;
    int i = b * 1024 + tid;
    int v = (i < NNODES) ? g_deg[i] : 0;
    int incl = v;
    #pragma unroll
    for (int off = 1; off < 32; off <<= 1) {
        int t = __shfl_up_sync(0xffffffff, incl, off);
        if (lane >= off) incl += t;
    }
    if (lane == 31) wsum[wid] = incl;
    __syncthreads();
    if (wid == 0) {
        int s = (lane < 32) ? wsum[lane] : 0;
        #pragma unroll
        for (int off = 1; off < 32; off <<= 1) {
            int t = __shfl_up_sync(0xffffffff, s, off);
            if (lane >= off) s += t;
        }
        wsum[lane] = s;
    }
    __syncthreads();
    if (i < NNODES) {
        int o = g_boff[b] + (wid ? wsum[wid - 1] : 0) + incl - v;  // exclusive
        g_rowptr[i] = o;
        g_cursor[i] = o;
        g_dinv[i]   = rsqrtf(1.0f + (float)v);
    }
}

__global__ void fill_csr_k(const int* __restrict__ ei) {
    int e4 = blockIdx.x * blockDim.x + threadIdx.x;
    if (e4 < NEDGES / 4) {
        int4 s = ((const int4*)ei)[e4];
        int4 d = ((const int4*)(ei + NEDGES))[e4];
        g_col[atomicAdd(&g_cursor[d.x], 1)] = s.x;
        g_col[atomicAdd(&g_cursor[d.y], 1)] = s.y;
        g_col[atomicAdd(&g_cursor[d.z], 1)] = s.z;
        g_col[atomicAdd(&g_cursor[d.w], 1)] = s.w;
    }
}

// ---------------- bf16 split helpers ----------------
// pack two bf16 (k, k+1) into one b32: low half = even k
__device__ __forceinline__ unsigned pack_bf16(float a, float b) {
    __nv_bfloat162 p = __floats2bfloat162_rn(a, b);   // .x=a, .y=b
    return *(unsigned*)&p;
}
__device__ __forceinline__ void split2(float v0, float v1, unsigned& hi, unsigned& lo) {
    __nv_bfloat16 h0 = __float2bfloat16_rn(v0);
    __nv_bfloat16 h1 = __float2bfloat16_rn(v1);
    float l0 = v0 - __bfloat162float(h0);
    float l1 = v1 - __bfloat162float(h1);
    __nv_bfloat162 hp; hp.x = h0; hp.y = h1;
    hi = *(unsigned*)&hp;
    lo = pack_bf16(l0, l1);
}

__device__ __forceinline__ void mma_bf16(
    float& c0, float& c1, float& c2, float& c3,
    unsigned a0, unsigned a1, unsigned a2, unsigned a3,
    unsigned b0, unsigned b1)
{
    asm volatile(
        "mma.sync.aligned.m16n8k16.row.col.f32.bf16.bf16.f32 "
        "{%0,%1,%2,%3}, {%4,%5,%6,%7}, {%8,%9}, {%0,%1,%2,%3};"
        : "+f"(c0), "+f"(c1), "+f"(c2), "+f"(c3)
        : "r"(a0), "r"(a1), "r"(a2), "r"(a3), "r"(b0), "r"(b1));
}

// ---------------- tensor GEMM: out[row] = (A[row,:] @ W) [* dinv[row]] -------
// BM=128, BK=16, 256 threads = 8 warps (MW x NW).
// bf16 hi/lo split, 3-term compensation (hi*hi + hi*lo + lo*hi), fp32 accum.
// Packed smem: [k2][m] / [k2][n], each b32 = bf16 pair (k=2*k2, 2*k2+1).
template <int FOUT, int MW, int NW, bool H16, bool SCALE>
__global__ __launch_bounds__(256) void gemm_tc_k(
    const float* __restrict__ Aext, int selA, int selO,
    const float* __restrict__ W)
{
    const int BM = 128, BK = 16, K2 = BK / 2;
    const int MT = BM / (16 * MW);
    const int NT = FOUT / (8 * NW);
    const int APAD = BM + 8;       // 136: conflict-free frag LDS
    const int WPAD = FOUT + 8;

    __shared__ unsigned Ap_hi[K2][APAD], Ap_lo[K2][APAD];
    __shared__ unsigned Wp_hi[K2][WPAD], Wp_lo[K2][WPAD];

    const float* A = (selA == 1) ? g_bufA : (selA == 2) ? g_bufB : Aext;
    float* out = (selO == 1) ? g_bufA : g_bufB;

    int tid  = threadIdx.x;
    int lane = tid & 31;
    int wid  = tid >> 5;
    int warp_m = wid % MW;
    int warp_n = wid / MW;
    int rb = blockIdx.x * BM;

    float c[MT][NT][4];
    #pragma unroll
    for (int mt = 0; mt < MT; mt++)
        #pragma unroll
        for (int nt = 0; nt < NT; nt++)
            #pragma unroll
            for (int q = 0; q < 4; q++) c[mt][nt][q] = 0.0f;

    for (int kt = 0; kt < FIN; kt += BK) {
        // A tile: 128 rows x 16 k; thread loads float4 (4 k at row r) -> 2 packed pairs
        #pragma unroll
        for (int t = 0; t < 2; t++) {
            int idx = tid + t * 256;          // 0..511
            int r = idx >> 2, q = idx & 3;    // row, k-quad
            int row = rb + r;
            float4 v = make_float4(0.f, 0.f, 0.f, 0.f);
            if (row < NNODES)
                v = *(const float4*)&A[(size_t)row * FIN + kt + q * 4];
            unsigned h, l;
            split2(v.x, v.y, h, l); Ap_hi[q * 2][r] = h;     Ap_lo[q * 2][r] = l;
            split2(v.z, v.w, h, l); Ap_hi[q * 2 + 1][r] = h; Ap_lo[q * 2 + 1][r] = l;
        }
        // W tile: 16 k x FOUT; thread loads rows 2k2, 2k2+1 at 4 n -> 4 packed pairs
        {
            int tasks = K2 * (FOUT / 4);      // 256 (FOUT=128) or 128 (FOUT=64)
            if (tid < tasks) {
                int k2 = tid / (FOUT / 4), q = tid % (FOUT / 4);
                float4 v0 = *(const float4*)&W[(size_t)(kt + 2 * k2) * FOUT + q * 4];
                float4 v1 = *(const float4*)&W[(size_t)(kt + 2 * k2 + 1) * FOUT + q * 4];
                unsigned h, l;
                split2(v0.x, v1.x, h, l); Wp_hi[k2][q * 4 + 0] = h; Wp_lo[k2][q * 4 + 0] = l;
                split2(v0.y, v1.y, h, l); Wp_hi[k2][q * 4 + 1] = h; Wp_lo[k2][q * 4 + 1] = l;
                split2(v0.z, v1.z, h, l); Wp_hi[k2][q * 4 + 2] = h; Wp_lo[k2][q * 4 + 2] = l;
                split2(v0.w, v1.w, h, l); Wp_hi[k2][q * 4 + 3] = h; Wp_lo[k2][q * 4 + 3] = l;
            }
        }
        __syncthreads();

        int t4 = lane & 3;        // k2 selector
        int g  = lane >> 2;       // group
        unsigned ahi[MT][4], alo[MT][4];
        #pragma unroll
        for (int mt = 0; mt < MT; mt++) {
            int m = warp_m * (MT * 16) + mt * 16 + g;
            ahi[mt][0] = Ap_hi[t4][m];         alo[mt][0] = Ap_lo[t4][m];
            ahi[mt][1] = Ap_hi[t4][m + 8];     alo[mt][1] = Ap_lo[t4][m + 8];
            ahi[mt][2] = Ap_hi[t4 + 4][m];     alo[mt][2] = Ap_lo[t4 + 4][m];
            ahi[mt][3] = Ap_hi[t4 + 4][m + 8]; alo[mt][3] = Ap_lo[t4 + 4][m + 8];
        }
        #pragma unroll
        for (int nt = 0; nt < NT; nt++) {
            int n = warp_n * (NT * 8) + nt * 8 + g;
            unsigned bh0 = Wp_hi[t4][n],     bh1 = Wp_hi[t4 + 4][n];
            unsigned bl0 = Wp_lo[t4][n],     bl1 = Wp_lo[t4 + 4][n];
            #pragma unroll
            for (int mt = 0; mt < MT; mt++) {
                mma_bf16(c[mt][nt][0], c[mt][nt][1], c[mt][nt][2], c[mt][nt][3],
                         ahi[mt][0], ahi[mt][1], ahi[mt][2], ahi[mt][3], bh0, bh1);
                mma_bf16(c[mt][nt][0], c[mt][nt][1], c[mt][nt][2], c[mt][nt][3],
                         ahi[mt][0], ahi[mt][1], ahi[mt][2], ahi[mt][3], bl0, bl1);
                mma_bf16(c[mt][nt][0], c[mt][nt][1], c[mt][nt][2], c[mt][nt][3],
                         alo[mt][0], alo[mt][1], alo[mt][2], alo[mt][3], bh0, bh1);
            }
        }
        __syncthreads();
    }

    // epilogue: optional dinv scale; fp16 or fp32 store
    #pragma unroll
    for (int mt = 0; mt < MT; mt++) {
        int r0 = rb + warp_m * (MT * 16) + mt * 16 + (lane >> 2);
        int colb = warp_n * (NT * 8) + (lane & 3) * 2;
        #pragma unroll
        for (int half = 0; half < 2; half++) {
            int row = half ? (r0 + 8) : r0;
            int q0 = half * 2;
            if (row < NNODES) {
                float d = SCALE ? g_dinv[row] : 1.0f;
                #pragma unroll
                for (int nt = 0; nt < NT; nt++) {
                    float vx = c[mt][nt][q0] * d, vy = c[mt][nt][q0 + 1] * d;
                    if (H16) {
                        *(__half2*)&g_bufH[(size_t)row * FOUT + colb + nt * 8] =
                            __floats2half2_rn(vx, vy);
                    } else {
                        *(float2*)&out[(size_t)row * FOUT + colb + nt * 8] =
                            make_float2(vx, vy);
                    }
                }
            }
        }
    }
}

// ---------------- aggregate fp16 hs (half-warp per dst, uint4/lane, F=128) ----
// SRCSCALE: hs holds unscaled h; multiply dinv[src] per edge (layer 1).
template <bool SRCSCALE>
__global__ __launch_bounds__(256) void agg128h_k(
    int selO, const float* __restrict__ bias,
    const float* __restrict__ gam, const float* __restrict__ bet,
    const float* __restrict__ mu,  const float* __restrict__ var)
{
    int dst  = blockIdx.x * 16 + (threadIdx.x >> 4);
    int lane = threadIdx.x & 15;
    if (dst >= NNODES) return;

    const uint4* hs = (const uint4*)g_bufH;   // row = 16 uint4 (8 fp16 each)
    float* outp = (selO == 1) ? g_bufA : g_bufB;

    int beg = g_rowptr[dst];
    int end = g_rowptr[dst + 1];
    float d = g_dinv[dst];

    float acc[8];
    {
        uint4 v = hs[(size_t)dst * 16 + lane];
        float2 f0 = __half22float2(*(__half2*)&v.x);
        float2 f1 = __half22float2(*(__half2*)&v.y);
        float2 f2 = __half22float2(*(__half2*)&v.z);
        float2 f3 = __half22float2(*(__half2*)&v.w);
        float sd = SRCSCALE ? d : 1.0f;
        acc[0] = f0.x * sd; acc[1] = f0.y * sd;
        acc[2] = f1.x * sd; acc[3] = f1.y * sd;
        acc[4] = f2.x * sd; acc[5] = f2.y * sd;
        acc[6] = f3.x * sd; acc[7] = f3.y * sd;
    }

    int e = beg;
    for (; e + 8 <= end; e += 8) {
        uint4 v[8]; float sc[8];
        #pragma unroll
        for (int u = 0; u < 8; u++) {
            int c = g_col[e + u];
            v[u] = hs[(size_t)c * 16 + lane];
            sc[u] = SRCSCALE ? g_dinv[c] : 1.0f;
        }
        #pragma unroll
        for (int u = 0; u < 8; u++) {
            float2 f0 = __half22float2(*(__half2*)&v[u].x);
            float2 f1 = __half22float2(*(__half2*)&v[u].y);
            float2 f2 = __half22float2(*(__half2*)&v[u].z);
            float2 f3 = __half22float2(*(__half2*)&v[u].w);
            acc[0] += f0.x * sc[u]; acc[1] += f0.y * sc[u];
            acc[2] += f1.x * sc[u]; acc[3] += f1.y * sc[u];
            acc[4] += f2.x * sc[u]; acc[5] += f2.y * sc[u];
            acc[6] += f3.x * sc[u]; acc[7] += f3.y * sc[u];
        }
    }
    for (; e < end; e++) {
        int c = g_col[e];
        uint4 v = hs[(size_t)c * 16 + lane];
        float sc = SRCSCALE ? g_dinv[c] : 1.0f;
        float2 f0 = __half22float2(*(__half2*)&v.x);
        float2 f1 = __half22float2(*(__half2*)&v.y);
        float2 f2 = __half22float2(*(__half2*)&v.z);
        float2 f3 = __half22float2(*(__half2*)&v.w);
        acc[0] += f0.x * sc; acc[1] += f0.y * sc;
        acc[2] += f1.x * sc; acc[3] += f1.y * sc;
        acc[4] += f2.x * sc; acc[5] += f2.y * sc;
        acc[6] += f3.x * sc; acc[7] += f3.y * sc;
    }

    float4 b0 = ((const float4*)bias)[lane * 2],     b1 = ((const float4*)bias)[lane * 2 + 1];
    float4 g0 = ((const float4*)gam)[lane * 2],      g1 = ((const float4*)gam)[lane * 2 + 1];
    float4 t0 = ((const float4*)bet)[lane * 2],      t1 = ((const float4*)bet)[lane * 2 + 1];
    float4 m0 = ((const float4*)mu)[lane * 2],       m1 = ((const float4*)mu)[lane * 2 + 1];
    float4 v0 = ((const float4*)var)[lane * 2],      v1 = ((const float4*)var)[lane * 2 + 1];
    float bb[8] = {b0.x, b0.y, b0.z, b0.w, b1.x, b1.y, b1.z, b1.w};
    float gg[8] = {g0.x, g0.y, g0.z, g0.w, g1.x, g1.y, g1.z, g1.w};
    float tt[8] = {t0.x, t0.y, t0.z, t0.w, t1.x, t1.y, t1.z, t1.w};
    float mm[8] = {m0.x, m0.y, m0.z, m0.w, m1.x, m1.y, m1.z, m1.w};
    float vv[8] = {v0.x, v0.y, v0.z, v0.w, v1.x, v1.y, v1.z, v1.w};

    float r[8];
    #pragma unroll
    for (int q = 0; q < 8; q++) {
        float val = acc[q] * d + bb[q];
        val = (val - mm[q]) * rsqrtf(vv[q] + BN_EPS) * gg[q] + tt[q];
        r[q] = val > 0.f ? val : 0.1f * val;
    }
    float4* orow = (float4*)&outp[(size_t)dst * 128 + lane * 8];
    orow[0] = make_float4(r[0], r[1], r[2], r[3]);
    orow[1] = make_float4(r[4], r[5], r[6], r[7]);
}

// ---------------- aggregate F=64 fp16 hs (half-warp per dst, uint2/lane) ------
__global__ __launch_bounds__(256) void agg64h_k(
    float* __restrict__ Oext, const float* __restrict__ bias)
{
    int dst  = blockIdx.x * 16 + (threadIdx.x >> 4);
    int lane = threadIdx.x & 15;
    if (dst >= NNODES) return;

    const uint2* hs = (const uint2*)g_bufH;   // row = 16 uint2 (4 fp16 each)

    int beg = g_rowptr[dst];
    int end = g_rowptr[dst + 1];

    float acc[4];
    {
        uint2 v = hs[(size_t)dst * 16 + lane];
        float2 f0 = __half22float2(*(__half2*)&v.x);
        float2 f1 = __half22float2(*(__half2*)&v.y);
        acc[0] = f0.x; acc[1] = f0.y; acc[2] = f1.x; acc[3] = f1.y;
    }
    int e = beg;
    for (; e + 8 <= end; e += 8) {
        uint2 v[8];
        #pragma unroll
        for (int u = 0; u < 8; u++)
            v[u] = hs[(size_t)g_col[e + u] * 16 + lane];
        #pragma unroll
        for (int u = 0; u < 8; u++) {
            float2 f0 = __half22float2(*(__half2*)&v[u].x);
            float2 f1 = __half22float2(*(__half2*)&v[u].y);
            acc[0] += f0.x; acc[1] += f0.y; acc[2] += f1.x; acc[3] += f1.y;
        }
    }
    for (; e < end; e++) {
        uint2 v = hs[(size_t)g_col[e] * 16 + lane];
        float2 f0 = __half22float2(*(__half2*)&v.x);
        float2 f1 = __half22float2(*(__half2*)&v.y);
        acc[0] += f0.x; acc[1] += f0.y; acc[2] += f1.x; acc[3] += f1.y;
    }

    float d = g_dinv[dst];
    float4 b4 = ((const float4*)bias)[lane];
    float4 r;
    r.x = acc[0] * d + b4.x;
    r.y = acc[1] * d + b4.y;
    r.z = acc[2] * d + b4.z;
    r.w = acc[3] * d + b4.w;
    ((float4*)Oext)[(size_t)dst * 16 + lane] = r;
}

// ---------------- launch ----------------
extern "C" void kernel_launch(void* const* d_in, const int* in_sizes, int n_in,
                              void* d_out, int out_size)
{
    const float* x   = (const float*)d_in[0];
    const int*   ei  = (const int*)d_in[1];
    const float* W1 = (const float*)d_in[2];
    const float* b1 = (const float*)d_in[3];
    const float* g1 = (const float*)d_in[4];
    const float* be1= (const float*)d_in[5];
    const float* m1 = (const float*)d_in[6];
    const float* v1 = (const float*)d_in[7];
    const float* W2 = (const float*)d_in[8];
    const float* b2 = (const float*)d_in[9];
    const float* g2 = (const float*)d_in[10];
    const float* be2= (const float*)d_in[11];
    const float* m2 = (const float*)d_in[12];
    const float* v2 = (const float*)d_in[13];
    const float* W3 = (const float*)d_in[14];
    const float* b3 = (const float*)d_in[15];
    float* out = (float*)d_out;

    // side stream + events, created once on the (non-captured) correctness call
    static cudaStream_t s2 = nullptr;
    static cudaEvent_t evF = nullptr, evJ = nullptr;
    if (s2 == nullptr) {
        cudaStreamCreateWithFlags(&s2, cudaStreamNonBlocking);
        cudaEventCreateWithFlags(&evF, cudaEventDisableTiming);
        cudaEventCreateWithFlags(&evJ, cudaEventDisableTiming);
    }

    const int gblk = (NNODES + 127) / 128;
    const int ablk = (NNODES + 15) / 16;

    // fork: CSR build on s2, concurrent with GEMM1 (which doesn't need dinv)
    cudaEventRecord(evF, 0);
    cudaStreamWaitEvent(s2, evF, 0);
    zero_deg_k<<<(NNODES + 255) / 256, 256, 0, s2>>>();
    deg_hist_k<<<(NEDGES / 4 + 255) / 256, 256, 0, s2>>>(ei);
    scan1_k<<<NCHUNK, 256, 0, s2>>>();
    scan2_k<<<1, 64, 0, s2>>>();
    scan3_k<<<NCHUNK, 1024, 0, s2>>>();
    fill_csr_k<<<(NEDGES / 4 + 255) / 256, 256, 0, s2>>>(ei);

    // layer 1 GEMM: x @ W1 -> H fp16 (unscaled)
    gemm_tc_k<128, 4, 2, true, false><<<gblk, 256>>>(x, 0, 2, W1);

    // join
    cudaEventRecord(evJ, s2);
    cudaStreamWaitEvent(0, evJ, 0);

    // layer 1 agg (applies dinv[src] inline), BN1 + leaky -> bufB fp32
    agg128h_k<true><<<ablk, 256>>>(2, b1, g1, be1, m1, v1);

    // layer 2: 128 -> 128, BN2 + leaky   (bufB -> H fp16 scaled ; agg -> bufB)
    gemm_tc_k<128, 4, 2, true, true><<<gblk, 256>>>(nullptr, 2, 2, W2);
    agg128h_k<false><<<ablk, 256>>>(2, b2, g2, be2, m2, v2);

    // layer 3: 128 -> 64, bias only      (bufB -> H fp16 scaled ; agg -> out)
    gemm_tc_k<64, 8, 1, true, true><<<gblk, 256>>>(nullptr, 2, 1, W3);
    agg64h_k<<<ablk, 256>>>(out, b3);
}

// round 9
// speedup vs baseline: 2.9958x; 1.0805x over previous
#include <cuda_runtime.h>
#include <cuda_fp16.h>
#include <cuda_bf16.h>

#define NNODES 50000
#define NEDGES 800000
#define FIN    128
#define BN_EPS 1e-5f
#define NCHUNK ((NNODES + 1023) / 1024)   // 49

// ---------------- scratch (device globals: no allocs allowed) ----------------
__device__ __half g_bufH[NNODES * 128];   // GEMM out (hs, fp16) -> agg gathers
__device__ __half g_bufG[NNODES * 128];   // agg out (fp16) -> next GEMM A
__device__ int    g_deg[NNODES];
__device__ int    g_rowptr[NNODES + 1];
__device__ int    g_rank[NEDGES];
__device__ int    g_col[NEDGES];
__device__ float  g_dinv[NNODES];
__device__ int    g_bsum[NCHUNK];
__device__ int    g_boff[NCHUNK];

// ---------------- CSR build ----------------
__global__ void zero_deg_k() {
    int i = blockIdx.x * blockDim.x + threadIdx.x;
    if (i < NNODES) g_deg[i] = 0;
}

// single atomic pass: count + per-edge rank within dst bucket
__global__ void hist_rank_k(const int* __restrict__ ei) {
    int e4 = blockIdx.x * blockDim.x + threadIdx.x;
    if (e4 < NEDGES / 4) {
        int4 d = ((const int4*)(ei + NEDGES))[e4];
        int4 r;
        r.x = atomicAdd(&g_deg[d.x], 1);
        r.y = atomicAdd(&g_deg[d.y], 1);
        r.z = atomicAdd(&g_deg[d.z], 1);
        r.w = atomicAdd(&g_deg[d.w], 1);
        ((int4*)g_rank)[e4] = r;
    }
}

// block sums of 1024-element chunks
__global__ void scan1_k() {
    __shared__ int ws[8];
    int b = blockIdx.x, tid = threadIdx.x, lane = tid & 31, wid = tid >> 5;
    int base = b * 1024 + tid * 4;
    int s = 0;
    #pragma unroll
    for (int u = 0; u < 4; u++) {
        int i = base + u;
        if (i < NNODES) s += g_deg[i];
    }
    #pragma unroll
    for (int off = 16; off > 0; off >>= 1)
        s += __shfl_down_sync(0xffffffff, s, off);
    if (lane == 0) ws[wid] = s;
    __syncthreads();
    if (tid == 0) {
        int t = 0;
        #pragma unroll
        for (int w = 0; w < 8; w++) t += ws[w];
        g_bsum[b] = t;
    }
}

// exclusive scan of NCHUNK block sums
__global__ void scan2_k() {
    __shared__ int s[64];
    int tid = threadIdx.x;
    s[tid] = (tid < NCHUNK) ? g_bsum[tid] : 0;
    __syncthreads();
    #pragma unroll
    for (int off = 1; off < 64; off <<= 1) {
        int t = (tid >= off) ? s[tid - off] : 0;
        __syncthreads();
        s[tid] += t;
        __syncthreads();
    }
    if (tid < NCHUNK) g_boff[tid] = s[tid] - g_bsum[tid];   // exclusive
    if (tid == 0) g_rowptr[NNODES] = NEDGES;
}

// per-chunk scan + write rowptr/dinv
__global__ void scan3_k() {
    __shared__ int wsum[32];
    int b = blockIdx.x, tid = threadIdx.x, lane = tid & 31, wid = tid >> 5;
    int i = b * 1024 + tid;
    int v = (i < NNODES) ? g_deg[i] : 0;
    int incl = v;
    #pragma unroll
    for (int off = 1; off < 32; off <<= 1) {
        int t = __shfl_up_sync(0xffffffff, incl, off);
        if (lane >= off) incl += t;
    }
    if (lane == 31) wsum[wid] = incl;
    __syncthreads();
    if (wid == 0) {
        int s = wsum[lane];
        #pragma unroll
        for (int off = 1; off < 32; off <<= 1) {
            int t = __shfl_up_sync(0xffffffff, s, off);
            if (lane >= off) s += t;
        }
        wsum[lane] = s;
    }
    __syncthreads();
    if (i < NNODES) {
        int o = g_boff[b] + (wid ? wsum[wid - 1] : 0) + incl - v;  // exclusive
        g_rowptr[i] = o;
        g_dinv[i]   = rsqrtf(1.0f + (float)v);
    }
}

// atomic-free scatter using precomputed ranks
__global__ void scatter_k(const int* __restrict__ ei) {
    int e4 = blockIdx.x * blockDim.x + threadIdx.x;
    if (e4 < NEDGES / 4) {
        int4 s = ((const int4*)ei)[e4];
        int4 d = ((const int4*)(ei + NEDGES))[e4];
        int4 r = ((const int4*)g_rank)[e4];
        g_col[g_rowptr[d.x] + r.x] = s.x;
        g_col[g_rowptr[d.y] + r.y] = s.y;
        g_col[g_rowptr[d.z] + r.z] = s.z;
        g_col[g_rowptr[d.w] + r.w] = s.w;
    }
}

// ---------------- bf16 split helpers (layer-1 GEMM) ----------------
__device__ __forceinline__ void split2b(float v0, float v1, unsigned& hi, unsigned& lo) {
    __nv_bfloat16 h0 = __float2bfloat16_rn(v0);
    __nv_bfloat16 h1 = __float2bfloat16_rn(v1);
    float l0 = v0 - __bfloat162float(h0);
    float l1 = v1 - __bfloat162float(h1);
    __nv_bfloat162 hp; hp.x = h0; hp.y = h1;
    hi = *(unsigned*)&hp;
    __nv_bfloat162 lp = __floats2bfloat162_rn(l0, l1);
    lo = *(unsigned*)&lp;
}

__device__ __forceinline__ void mma_bf16(
    float& c0, float& c1, float& c2, float& c3,
    unsigned a0, unsigned a1, unsigned a2, unsigned a3,
    unsigned b0, unsigned b1)
{
    asm volatile(
        "mma.sync.aligned.m16n8k16.row.col.f32.bf16.bf16.f32 "
        "{%0,%1,%2,%3}, {%4,%5,%6,%7}, {%8,%9}, {%0,%1,%2,%3};"
        : "+f"(c0), "+f"(c1), "+f"(c2), "+f"(c3)
        : "r"(a0), "r"(a1), "r"(a2), "r"(a3), "r"(b0), "r"(b1));
}

// ---------------- fp16 helpers (layer-2/3 GEMMs) ----------------
__device__ __forceinline__ void split2h(float v0, float v1, unsigned& hi, unsigned& lo) {
    __half h0 = __float2half_rn(v0);
    __half h1 = __float2half_rn(v1);
    float l0 = v0 - __half2float(h0);
    float l1 = v1 - __half2float(h1);
    __half2 hp; hp.x = h0; hp.y = h1;
    hi = *(unsigned*)&hp;
    __half2 lp = __floats2half2_rn(l0, l1);
    lo = *(unsigned*)&lp;
}

__device__ __forceinline__ void mma_f16(
    float& c0, float& c1, float& c2, float& c3,
    unsigned a0, unsigned a1, unsigned a2, unsigned a3,
    unsigned b0, unsigned b1)
{
    asm volatile(
        "mma.sync.aligned.m16n8k16.row.col.f32.f16.f16.f32 "
        "{%0,%1,%2,%3}, {%4,%5,%6,%7}, {%8,%9}, {%0,%1,%2,%3};"
        : "+f"(c0), "+f"(c1), "+f"(c2), "+f"(c3)
        : "r"(a0), "r"(a1), "r"(a2), "r"(a3), "r"(b0), "r"(b1));
}

// ------------- layer-1 GEMM: g_bufH = (x @ W1), bf16 3-term, fp16 out --------
__global__ __launch_bounds__(256) void gemm1_k(
    const float* __restrict__ A, const float* __restrict__ W)
{
    const int FOUT = 128, MW = 4, NW = 2;
    const int BM = 128, BK = 16, K2 = BK / 2;
    const int MT = BM / (16 * MW);      // 2
    const int NT = FOUT / (8 * NW);     // 8
    const int APAD = BM + 8;
    const int WPAD = FOUT + 8;

    __shared__ unsigned Ap_hi[K2][APAD], Ap_lo[K2][APAD];
    __shared__ unsigned Wp_hi[K2][WPAD], Wp_lo[K2][WPAD];

    int tid  = threadIdx.x;
    int lane = tid & 31;
    int wid  = tid >> 5;
    int warp_m = wid % MW;
    int warp_n = wid / MW;
    int rb = blockIdx.x * BM;

    float c[MT][NT][4];
    #pragma unroll
    for (int mt = 0; mt < MT; mt++)
        #pragma unroll
        for (int nt = 0; nt < NT; nt++)
            #pragma unroll
            for (int q = 0; q < 4; q++) c[mt][nt][q] = 0.0f;

    for (int kt = 0; kt < FIN; kt += BK) {
        #pragma unroll
        for (int t = 0; t < 2; t++) {
            int idx = tid + t * 256;
            int r = idx >> 2, q = idx & 3;
            int row = rb + r;
            float4 v = make_float4(0.f, 0.f, 0.f, 0.f);
            if (row < NNODES)
                v = *(const float4*)&A[(size_t)row * FIN + kt + q * 4];
            unsigned h, l;
            split2b(v.x, v.y, h, l); Ap_hi[q * 2][r] = h;     Ap_lo[q * 2][r] = l;
            split2b(v.z, v.w, h, l); Ap_hi[q * 2 + 1][r] = h; Ap_lo[q * 2 + 1][r] = l;
        }
        {
            int k2 = tid >> 5, q = tid & 31;   // 8 x 32 = 256 tasks
            float4 v0 = *(const float4*)&W[(size_t)(kt + 2 * k2) * FOUT + q * 4];
            float4 v1 = *(const float4*)&W[(size_t)(kt + 2 * k2 + 1) * FOUT + q * 4];
            unsigned h, l;
            split2b(v0.x, v1.x, h, l); Wp_hi[k2][q * 4 + 0] = h; Wp_lo[k2][q * 4 + 0] = l;
            split2b(v0.y, v1.y, h, l); Wp_hi[k2][q * 4 + 1] = h; Wp_lo[k2][q * 4 + 1] = l;
            split2b(v0.z, v1.z, h, l); Wp_hi[k2][q * 4 + 2] = h; Wp_lo[k2][q * 4 + 2] = l;
            split2b(v0.w, v1.w, h, l); Wp_hi[k2][q * 4 + 3] = h; Wp_lo[k2][q * 4 + 3] = l;
        }
        __syncthreads();

        int t4 = lane & 3;
        int g  = lane >> 2;
        unsigned ahi[MT][4], alo[MT][4];
        #pragma unroll
        for (int mt = 0; mt < MT; mt++) {
            int m = warp_m * (MT * 16) + mt * 16 + g;
            ahi[mt][0] = Ap_hi[t4][m];         alo[mt][0] = Ap_lo[t4][m];
            ahi[mt][1] = Ap_hi[t4][m + 8];     alo[mt][1] = Ap_lo[t4][m + 8];
            ahi[mt][2] = Ap_hi[t4 + 4][m];     alo[mt][2] = Ap_lo[t4 + 4][m];
            ahi[mt][3] = Ap_hi[t4 + 4][m + 8]; alo[mt][3] = Ap_lo[t4 + 4][m + 8];
        }
        #pragma unroll
        for (int nt = 0; nt < NT; nt++) {
            int n = warp_n * (NT * 8) + nt * 8 + g;
            unsigned bh0 = Wp_hi[t4][n], bh1 = Wp_hi[t4 + 4][n];
            unsigned bl0 = Wp_lo[t4][n], bl1 = Wp_lo[t4 + 4][n];
            #pragma unroll
            for (int mt = 0; mt < MT; mt++) {
                mma_bf16(c[mt][nt][0], c[mt][nt][1], c[mt][nt][2], c[mt][nt][3],
                         ahi[mt][0], ahi[mt][1], ahi[mt][2], ahi[mt][3], bh0, bh1);
                mma_bf16(c[mt][nt][0], c[mt][nt][1], c[mt][nt][2], c[mt][nt][3],
                         ahi[mt][0], ahi[mt][1], ahi[mt][2], ahi[mt][3], bl0, bl1);
                mma_bf16(c[mt][nt][0], c[mt][nt][1], c[mt][nt][2], c[mt][nt][3],
                         alo[mt][0], alo[mt][1], alo[mt][2], alo[mt][3], bh0, bh1);
            }
        }
        __syncthreads();
    }

    // epilogue: unscaled fp16 store (agg1 applies dinv[src])
    #pragma unroll
    for (int mt = 0; mt < MT; mt++) {
        int r0 = rb + warp_m * (MT * 16) + mt * 16 + (lane >> 2);
        int colb = warp_n * (NT * 8) + (lane & 3) * 2;
        #pragma unroll
        for (int half = 0; half < 2; half++) {
            int row = half ? (r0 + 8) : r0;
            int q0 = half * 2;
            if (row < NNODES) {
                #pragma unroll
                for (int nt = 0; nt < NT; nt++)
                    *(__half2*)&g_bufH[(size_t)row * FOUT + colb + nt * 8] =
                        __floats2half2_rn(c[mt][nt][q0], c[mt][nt][q0 + 1]);
            }
        }
    }
}

// ------- layer-2/3 GEMM: g_bufH = (g_bufG @ W) * dinv, fp16 A, 2-term W ------
template <int FOUT, int MW, int NW>
__global__ __launch_bounds__(256) void gemm_h_k(const float* __restrict__ W)
{
    const int BM = 128, BK = 16, K2 = BK / 2;
    const int MT = BM / (16 * MW);
    const int NT = FOUT / (8 * NW);
    const int APAD = BM + 8;
    const int WPAD = FOUT + 8;

    __shared__ unsigned Ap[K2][APAD];
    __shared__ unsigned Wp_hi[K2][WPAD], Wp_lo[K2][WPAD];

    int tid  = threadIdx.x;
    int lane = tid & 31;
    int wid  = tid >> 5;
    int warp_m = wid % MW;
    int warp_n = wid / MW;
    int rb = blockIdx.x * BM;

    float c[MT][NT][4];
    #pragma unroll
    for (int mt = 0; mt < MT; mt++)
        #pragma unroll
        for (int nt = 0; nt < NT; nt++)
            #pragma unroll
            for (int q = 0; q < 4; q++) c[mt][nt][q] = 0.0f;

    for (int kt = 0; kt < FIN; kt += BK) {
        // A tile: fp16 direct copy, 128 rows x 16 k = 256 uint4, 1/thread
        {
            int r = tid & 127, q = tid >> 7;       // q in {0,1}
            int row = rb + r;
            uint4 v = make_uint4(0, 0, 0, 0);
            if (row < NNODES)
                v = *(const uint4*)&g_bufG[(size_t)row * FIN + kt + q * 8];
            Ap[q * 4 + 0][r] = v.x;
            Ap[q * 4 + 1][r] = v.y;
            Ap[q * 4 + 2][r] = v.z;
            Ap[q * 4 + 3][r] = v.w;
        }
        // W tile: fp16 hi/lo split
        {
            int tasks = K2 * (FOUT / 4);
            if (tid < tasks) {
                int k2 = tid / (FOUT / 4), q = tid % (FOUT / 4);
                float4 v0 = *(const float4*)&W[(size_t)(kt + 2 * k2) * FOUT + q * 4];
                float4 v1 = *(const float4*)&W[(size_t)(kt + 2 * k2 + 1) * FOUT + q * 4];
                unsigned h, l;
                split2h(v0.x, v1.x, h, l); Wp_hi[k2][q * 4 + 0] = h; Wp_lo[k2][q * 4 + 0] = l;
                split2h(v0.y, v1.y, h, l); Wp_hi[k2][q * 4 + 1] = h; Wp_lo[k2][q * 4 + 1] = l;
                split2h(v0.z, v1.z, h, l); Wp_hi[k2][q * 4 + 2] = h; Wp_lo[k2][q * 4 + 2] = l;
                split2h(v0.w, v1.w, h, l); Wp_hi[k2][q * 4 + 3] = h; Wp_lo[k2][q * 4 + 3] = l;
            }
        }
        __syncthreads();

        int t4 = lane & 3;
        int g  = lane >> 2;
        unsigned a[MT][4];
        #pragma unroll
        for (int mt = 0; mt < MT; mt++) {
            int m = warp_m * (MT * 16) + mt * 16 + g;
            a[mt][0] = Ap[t4][m];
            a[mt][1] = Ap[t4][m + 8];
            a[mt][2] = Ap[t4 + 4][m];
            a[mt][3] = Ap[t4 + 4][m + 8];
        }
        #pragma unroll
        for (int nt = 0; nt < NT; nt++) {
            int n = warp_n * (NT * 8) + nt * 8 + g;
            unsigned bh0 = Wp_hi[t4][n], bh1 = Wp_hi[t4 + 4][n];
            unsigned bl0 = Wp_lo[t4][n], bl1 = Wp_lo[t4 + 4][n];
            #pragma unroll
            for (int mt = 0; mt < MT; mt++) {
                mma_f16(c[mt][nt][0], c[mt][nt][1], c[mt][nt][2], c[mt][nt][3],
                        a[mt][0], a[mt][1], a[mt][2], a[mt][3], bh0, bh1);
                mma_f16(c[mt][nt][0], c[mt][nt][1], c[mt][nt][2], c[mt][nt][3],
                        a[mt][0], a[mt][1], a[mt][2], a[mt][3], bl0, bl1);
            }
        }
        __syncthreads();
    }

    // epilogue: dinv scale, fp16 store
    #pragma unroll
    for (int mt = 0; mt < MT; mt++) {
        int r0 = rb + warp_m * (MT * 16) + mt * 16 + (lane >> 2);
        int colb = warp_n * (NT * 8) + (lane & 3) * 2;
        #pragma unroll
        for (int half = 0; half < 2; half++) {
            int row = half ? (r0 + 8) : r0;
            int q0 = half * 2;
            if (row < NNODES) {
                float d = g_dinv[row];
                #pragma unroll
                for (int nt = 0; nt < NT; nt++)
                    *(__half2*)&g_bufH[(size_t)row * FOUT + colb + nt * 8] =
                        __floats2half2_rn(c[mt][nt][q0] * d, c[mt][nt][q0 + 1] * d);
            }
        }
    }
}

// ---------------- aggregate fp16 hs (half-warp per dst, uint4/lane, F=128) ----
// SRCSCALE: hs holds unscaled h; multiply dinv[src] per edge (layer 1).
// Output: fp16 to g_bufG (next GEMM's A).
template <bool SRCSCALE>
__global__ __launch_bounds__(256) void agg128h_k(
    const float* __restrict__ bias,
    const float* __restrict__ gam, const float* __restrict__ bet,
    const float* __restrict__ mu,  const float* __restrict__ var)
{
    int dst  = blockIdx.x * 16 + (threadIdx.x >> 4);
    int lane = threadIdx.x & 15;
    if (dst >= NNODES) return;

    const uint4* hs = (const uint4*)g_bufH;   // row = 16 uint4 (8 fp16 each)

    int beg = g_rowptr[dst];
    int end = g_rowptr[dst + 1];
    float d = g_dinv[dst];

    float acc[8];
    {
        uint4 v = hs[(size_t)dst * 16 + lane];
        float2 f0 = __half22float2(*(__half2*)&v.x);
        float2 f1 = __half22float2(*(__half2*)&v.y);
        float2 f2 = __half22float2(*(__half2*)&v.z);
        float2 f3 = __half22float2(*(__half2*)&v.w);
        float sd = SRCSCALE ? d : 1.0f;
        acc[0] = f0.x * sd; acc[1] = f0.y * sd;
        acc[2] = f1.x * sd; acc[3] = f1.y * sd;
        acc[4] = f2.x * sd; acc[5] = f2.y * sd;
        acc[6] = f3.x * sd; acc[7] = f3.y * sd;
    }

    int e = beg;
    for (; e + 8 <= end; e += 8) {
        uint4 v[8]; float sc[8];
        #pragma unroll
        for (int u = 0; u < 8; u++) {
            int c = g_col[e + u];
            v[u] = hs[(size_t)c * 16 + lane];
            sc[u] = SRCSCALE ? g_dinv[c] : 1.0f;
        }
        #pragma unroll
        for (int u = 0; u < 8; u++) {
            float2 f0 = __half22float2(*(__half2*)&v[u].x);
            float2 f1 = __half22float2(*(__half2*)&v[u].y);
            float2 f2 = __half22float2(*(__half2*)&v[u].z);
            float2 f3 = __half22float2(*(__half2*)&v[u].w);
            acc[0] += f0.x * sc[u]; acc[1] += f0.y * sc[u];
            acc[2] += f1.x * sc[u]; acc[3] += f1.y * sc[u];
            acc[4] += f2.x * sc[u]; acc[5] += f2.y * sc[u];
            acc[6] += f3.x * sc[u]; acc[7] += f3.y * sc[u];
        }
    }
    for (; e < end; e++) {
        int c = g_col[e];
        uint4 v = hs[(size_t)c * 16 + lane];
        float sc = SRCSCALE ? g_dinv[c] : 1.0f;
        float2 f0 = __half22float2(*(__half2*)&v.x);
        float2 f1 = __half22float2(*(__half2*)&v.y);
        float2 f2 = __half22float2(*(__half2*)&v.z);
        float2 f3 = __half22float2(*(__half2*)&v.w);
        acc[0] += f0.x * sc; acc[1] += f0.y * sc;
        acc[2] += f1.x * sc; acc[3] += f1.y * sc;
        acc[4] += f2.x * sc; acc[5] += f2.y * sc;
        acc[6] += f3.x * sc; acc[7] += f3.y * sc;
    }

    float4 b0 = ((const float4*)bias)[lane * 2], b1 = ((const float4*)bias)[lane * 2 + 1];
    float4 g0 = ((const float4*)gam)[lane * 2],  g1 = ((const float4*)gam)[lane * 2 + 1];
    float4 t0 = ((const float4*)bet)[lane * 2],  t1 = ((const float4*)bet)[lane * 2 + 1];
    float4 m0 = ((const float4*)mu)[lane * 2],   m1 = ((const float4*)mu)[lane * 2 + 1];
    float4 v0 = ((const float4*)var)[lane * 2],  v1 = ((const float4*)var)[lane * 2 + 1];
    float bb[8] = {b0.x, b0.y, b0.z, b0.w, b1.x, b1.y, b1.z, b1.w};
    float gg[8] = {g0.x, g0.y, g0.z, g0.w, g1.x, g1.y, g1.z, g1.w};
    float tt[8] = {t0.x, t0.y, t0.z, t0.w, t1.x, t1.y, t1.z, t1.w};
    float mm[8] = {m0.x, m0.y, m0.z, m0.w, m1.x, m1.y, m1.z, m1.w};
    float vv[8] = {v0.x, v0.y, v0.z, v0.w, v1.x, v1.y, v1.z, v1.w};

    float r[8];
    #pragma unroll
    for (int q = 0; q < 8; q++) {
        float val = acc[q] * d + bb[q];
        val = (val - mm[q]) * rsqrtf(vv[q] + BN_EPS) * gg[q] + tt[q];
        r[q] = val > 0.f ? val : 0.1f * val;
    }
    uint4 o;
    *(__half2*)&o.x = __floats2half2_rn(r[0], r[1]);
    *(__half2*)&o.y = __floats2half2_rn(r[2], r[3]);
    *(__half2*)&o.z = __floats2half2_rn(r[4], r[5]);
    *(__half2*)&o.w = __floats2half2_rn(r[6], r[7]);
    ((uint4*)g_bufG)[(size_t)dst * 16 + lane] = o;
}

// ---------------- aggregate F=64 fp16 hs (half-warp per dst, uint2/lane) ------
__global__ __launch_bounds__(256) void agg64h_k(
    float* __restrict__ Oext, const float* __restrict__ bias)
{
    int dst  = blockIdx.x * 16 + (threadIdx.x >> 4);
    int lane = threadIdx.x & 15;
    if (dst >= NNODES) return;

    const uint2* hs = (const uint2*)g_bufH;   // row = 16 uint2 (4 fp16 each)

    int beg = g_rowptr[dst];
    int end = g_rowptr[dst + 1];

    float acc[4];
    {
        uint2 v = hs[(size_t)dst * 16 + lane];
        float2 f0 = __half22float2(*(__half2*)&v.x);
        float2 f1 = __half22float2(*(__half2*)&v.y);
        acc[0] = f0.x; acc[1] = f0.y; acc[2] = f1.x; acc[3] = f1.y;
    }
    int e = beg;
    for (; e + 8 <= end; e += 8) {
        uint2 v[8];
        #pragma unroll
        for (int u = 0; u < 8; u++)
            v[u] = hs[(size_t)g_col[e + u] * 16 + lane];
        #pragma unroll
        for (int u = 0; u < 8; u++) {
            float2 f0 = __half22float2(*(__half2*)&v[u].x);
            float2 f1 = __half22float2(*(__half2*)&v[u].y);
            acc[0] += f0.x; acc[1] += f0.y; acc[2] += f1.x; acc[3] += f1.y;
        }
    }
    for (; e < end; e++) {
        uint2 v = hs[(size_t)g_col[e] * 16 + lane];
        float2 f0 = __half22float2(*(__half2*)&v.x);
        float2 f1 = __half22float2(*(__half2*)&v.y);
        acc[0] += f0.x; acc[1] += f0.y; acc[2] += f1.x; acc[3] += f1.y;
    }

    float d = g_dinv[dst];
    float4 b4 = ((const float4*)bias)[lane];
    float4 r;
    r.x = acc[0] * d + b4.x;
    r.y = acc[1] * d + b4.y;
    r.z = acc[2] * d + b4.z;
    r.w = acc[3] * d + b4.w;
    ((float4*)Oext)[(size_t)dst * 16 + lane] = r;
}

// ---------------- launch ----------------
extern "C" void kernel_launch(void* const* d_in, const int* in_sizes, int n_in,
                              void* d_out, int out_size)
{
    const float* x   = (const float*)d_in[0];
    const int*   ei  = (const int*)d_in[1];
    const float* W1 = (const float*)d_in[2];
    const float* b1 = (const float*)d_in[3];
    const float* g1 = (const float*)d_in[4];
    const float* be1= (const float*)d_in[5];
    const float* m1 = (const float*)d_in[6];
    const float* v1 = (const float*)d_in[7];
    const float* W2 = (const float*)d_in[8];
    const float* b2 = (const float*)d_in[9];
    const float* g2 = (const float*)d_in[10];
    const float* be2= (const float*)d_in[11];
    const float* m2 = (const float*)d_in[12];
    const float* v2 = (const float*)d_in[13];
    const float* W3 = (const float*)d_in[14];
    const float* b3 = (const float*)d_in[15];
    float* out = (float*)d_out;

    // side stream + events, created once on the (non-captured) correctness call
    static cudaStream_t s2 = nullptr;
    static cudaEvent_t evF = nullptr, evJ = nullptr;
    if (s2 == nullptr) {
        cudaStreamCreateWithFlags(&s2, cudaStreamNonBlocking);
        cudaEventCreateWithFlags(&evF, cudaEventDisableTiming);
        cudaEventCreateWithFlags(&evJ, cudaEventDisableTiming);
    }

    const int gblk = (NNODES + 127) / 128;
    const int ablk = (NNODES + 15) / 16;

    // fork: CSR build on s2, concurrent with GEMM1
    cudaEventRecord(evF, 0);
    cudaStreamWaitEvent(s2, evF, 0);
    zero_deg_k<<<(NNODES + 255) / 256, 256, 0, s2>>>();
    hist_rank_k<<<(NEDGES / 4 + 255) / 256, 256, 0, s2>>>(ei);
    scan1_k<<<NCHUNK, 256, 0, s2>>>();
    scan2_k<<<1, 64, 0, s2>>>();
    scan3_k<<<NCHUNK, 1024, 0, s2>>>();
    scatter_k<<<(NEDGES / 4 + 255) / 256, 256, 0, s2>>>(ei);

    // layer 1 GEMM: x @ W1 -> g_bufH fp16 (unscaled)
    gemm1_k<<<gblk, 256>>>(x, W1);

    // join
    cudaEventRecord(evJ, s2);
    cudaStreamWaitEvent(0, evJ, 0);

    // layer 1 agg (applies dinv[src] inline), BN1 + leaky -> g_bufG fp16
    agg128h_k<true><<<ablk, 256>>>(b1, g1, be1, m1, v1);

    // layer 2: fp16 GEMM (g_bufG @ W2)*dinv -> g_bufH ; agg -> g_bufG
    gemm_h_k<128, 4, 2><<<gblk, 256>>>(W2);
    agg128h_k<false><<<ablk, 256>>>(b2, g2, be2, m2, v2);

    // layer 3: fp16 GEMM (g_bufG @ W3)*dinv -> g_bufH ; agg -> out fp32
    gemm_h_k<64, 8, 1><<<gblk, 256>>>(W3);
    agg64h_k<<<ablk, 256>>>(out, b3);
}

// round 10
// speedup vs baseline: 3.0481x; 1.0175x over previous
#include <cuda_runtime.h>
#include <cuda_fp16.h>
#include <cuda_bf16.h>

#define NNODES 50000
#define NEDGES 800000
#define FIN    128
#define BN_EPS 1e-5f
#define NCHUNK ((NNODES + 1023) / 1024)   // 49

// ---------------- scratch (device globals: no allocs allowed) ----------------
__device__ __half g_bufH[NNODES * 128];   // GEMM out (hs, fp16) -> agg gathers
__device__ __half g_bufG[NNODES * 128];   // agg out (fp16) -> next GEMM A
__device__ int    g_deg[NNODES];          // zero at entry (re-zeroed by scanB)
__device__ int    g_rowptr[NNODES + 1];
__device__ unsigned short g_rank16[NEDGES];
__device__ int    g_col[NEDGES];
__device__ float  g_dinv[NNODES];
__device__ int    g_bsum[NCHUNK];

// ---------------- CSR build ----------------
// single atomic pass: count + per-edge rank within dst bucket (u16)
__global__ void hist_rank_k(const int* __restrict__ ei) {
    int e4 = blockIdx.x * blockDim.x + threadIdx.x;
    if (e4 < NEDGES / 4) {
        int4 d = ((const int4*)(ei + NEDGES))[e4];
        ushort4 r;
        r.x = (unsigned short)atomicAdd(&g_deg[d.x], 1);
        r.y = (unsigned short)atomicAdd(&g_deg[d.y], 1);
        r.z = (unsigned short)atomicAdd(&g_deg[d.z], 1);
        r.w = (unsigned short)atomicAdd(&g_deg[d.w], 1);
        ((ushort4*)g_rank16)[e4] = r;
    }
}

// block sums of 1024-element chunks
__global__ void scan1_k() {
    __shared__ int ws[8];
    int b = blockIdx.x, tid = threadIdx.x, lane = tid & 31, wid = tid >> 5;
    int base = b * 1024 + tid * 4;
    int s = 0;
    #pragma unroll
    for (int u = 0; u < 4; u++) {
        int i = base + u;
        if (i < NNODES) s += g_deg[i];
    }
    #pragma unroll
    for (int off = 16; off > 0; off >>= 1)
        s += __shfl_down_sync(0xffffffff, s, off);
    if (lane == 0) ws[wid] = s;
    __syncthreads();
    if (tid == 0) {
        int t = 0;
        #pragma unroll
        for (int w = 0; w < 8; w++) t += ws[w];
        g_bsum[b] = t;
    }
}

// per-chunk scan; each block derives its own carry from g_bsum; zeroes g_deg
__global__ void scanB_k() {
    __shared__ int wsum[32];
    __shared__ int carry;
    int b = blockIdx.x, tid = threadIdx.x, lane = tid & 31, wid = tid >> 5;

    // warp 0: exclusive prefix of block sums (NCHUNK=49 < 64)
    if (wid == 0) {
        int v0 = (lane < b) ? g_bsum[lane] : 0;
        int v1 = (lane + 32 < b) ? g_bsum[lane + 32] : 0;
        int s = v0 + v1;
        #pragma unroll
        for (int off = 16; off > 0; off >>= 1)
            s += __shfl_down_sync(0xffffffff, s, off);
        if (lane == 0) carry = s;
    }

    int i = b * 1024 + tid;
    int v = (i < NNODES) ? g_deg[i] : 0;
    int incl = v;
    #pragma unroll
    for (int off = 1; off < 32; off <<= 1) {
        int t = __shfl_up_sync(0xffffffff, incl, off);
        if (lane >= off) incl += t;
    }
    if (lane == 31) wsum[wid] = incl;
    __syncthreads();
    if (wid == 0) {
        int s = wsum[lane];
        #pragma unroll
        for (int off = 1; off < 32; off <<= 1) {
            int t = __shfl_up_sync(0xffffffff, s, off);
            if (lane >= off) s += t;
        }
        wsum[lane] = s;
    }
    __syncthreads();
    if (i < NNODES) {
        int o = carry + (wid ? wsum[wid - 1] : 0) + incl - v;  // exclusive
        g_rowptr[i] = o;
        g_dinv[i]   = rsqrtf(1.0f + (float)v);
        g_deg[i]    = 0;                  // restore invariant for next call
    }
    if (b == 0 && tid == 0) g_rowptr[NNODES] = NEDGES;
}

// atomic-free scatter using precomputed u16 ranks
__global__ void scatter_k(const int* __restrict__ ei) {
    int e4 = blockIdx.x * blockDim.x + threadIdx.x;
    if (e4 < NEDGES / 4) {
        int4 s = ((const int4*)ei)[e4];
        int4 d = ((const int4*)(ei + NEDGES))[e4];
        ushort4 r = ((const ushort4*)g_rank16)[e4];
        g_col[g_rowptr[d.x] + r.x] = s.x;
        g_col[g_rowptr[d.y] + r.y] = s.y;
        g_col[g_rowptr[d.z] + r.z] = s.z;
        g_col[g_rowptr[d.w] + r.w] = s.w;
    }
}

// ---------------- bf16 split helpers (layer-1 GEMM) ----------------
__device__ __forceinline__ void split2b(float v0, float v1, unsigned& hi, unsigned& lo) {
    __nv_bfloat16 h0 = __float2bfloat16_rn(v0);
    __nv_bfloat16 h1 = __float2bfloat16_rn(v1);
    float l0 = v0 - __bfloat162float(h0);
    float l1 = v1 - __bfloat162float(h1);
    __nv_bfloat162 hp; hp.x = h0; hp.y = h1;
    hi = *(unsigned*)&hp;
    __nv_bfloat162 lp = __floats2bfloat162_rn(l0, l1);
    lo = *(unsigned*)&lp;
}

__device__ __forceinline__ void mma_bf16(
    float& c0, float& c1, float& c2, float& c3,
    unsigned a0, unsigned a1, unsigned a2, unsigned a3,
    unsigned b0, unsigned b1)
{
    asm volatile(
        "mma.sync.aligned.m16n8k16.row.col.f32.bf16.bf16.f32 "
        "{%0,%1,%2,%3}, {%4,%5,%6,%7}, {%8,%9}, {%0,%1,%2,%3};"
        : "+f"(c0), "+f"(c1), "+f"(c2), "+f"(c3)
        : "r"(a0), "r"(a1), "r"(a2), "r"(a3), "r"(b0), "r"(b1));
}

// ---------------- fp16 helpers (layer-2/3 GEMMs) ----------------
__device__ __forceinline__ void split2h(float v0, float v1, unsigned& hi, unsigned& lo) {
    __half h0 = __float2half_rn(v0);
    __half h1 = __float2half_rn(v1);
    float l0 = v0 - __half2float(h0);
    float l1 = v1 - __half2float(h1);
    __half2 hp; hp.x = h0; hp.y = h1;
    hi = *(unsigned*)&hp;
    __half2 lp = __floats2half2_rn(l0, l1);
    lo = *(unsigned*)&lp;
}

__device__ __forceinline__ void mma_f16(
    float& c0, float& c1, float& c2, float& c3,
    unsigned a0, unsigned a1, unsigned a2, unsigned a3,
    unsigned b0, unsigned b1)
{
    asm volatile(
        "mma.sync.aligned.m16n8k16.row.col.f32.f16.f16.f32 "
        "{%0,%1,%2,%3}, {%4,%5,%6,%7}, {%8,%9}, {%0,%1,%2,%3};"
        : "+f"(c0), "+f"(c1), "+f"(c2), "+f"(c3)
        : "r"(a0), "r"(a1), "r"(a2), "r"(a3), "r"(b0), "r"(b1));
}

// ------------- layer-1 GEMM: g_bufH = (x @ W1), bf16 3-term, fp16 out --------
__global__ __launch_bounds__(256) void gemm1_k(
    const float* __restrict__ A, const float* __restrict__ W)
{
    const int FOUT = 128, MW = 4, NW = 2;
    const int BM = 128, BK = 16, K2 = BK / 2;
    const int MT = BM / (16 * MW);      // 2
    const int NT = FOUT / (8 * NW);     // 8
    const int APAD = BM + 8;
    const int WPAD = FOUT + 8;

    __shared__ unsigned Ap_hi[K2][APAD], Ap_lo[K2][APAD];
    __shared__ unsigned Wp_hi[K2][WPAD], Wp_lo[K2][WPAD];

    int tid  = threadIdx.x;
    int lane = tid & 31;
    int wid  = tid >> 5;
    int warp_m = wid % MW;
    int warp_n = wid / MW;
    int rb = blockIdx.x * BM;

    float c[MT][NT][4];
    #pragma unroll
    for (int mt = 0; mt < MT; mt++)
        #pragma unroll
        for (int nt = 0; nt < NT; nt++)
            #pragma unroll
            for (int q = 0; q < 4; q++) c[mt][nt][q] = 0.0f;

    for (int kt = 0; kt < FIN; kt += BK) {
        #pragma unroll
        for (int t = 0; t < 2; t++) {
            int idx = tid + t * 256;
            int r = idx >> 2, q = idx & 3;
            int row = rb + r;
            float4 v = make_float4(0.f, 0.f, 0.f, 0.f);
            if (row < NNODES)
                v = *(const float4*)&A[(size_t)row * FIN + kt + q * 4];
            unsigned h, l;
            split2b(v.x, v.y, h, l); Ap_hi[q * 2][r] = h;     Ap_lo[q * 2][r] = l;
            split2b(v.z, v.w, h, l); Ap_hi[q * 2 + 1][r] = h; Ap_lo[q * 2 + 1][r] = l;
        }
        {
            int k2 = tid >> 5, q = tid & 31;   // 8 x 32 = 256 tasks
            float4 v0 = *(const float4*)&W[(size_t)(kt + 2 * k2) * FOUT + q * 4];
            float4 v1 = *(const float4*)&W[(size_t)(kt + 2 * k2 + 1) * FOUT + q * 4];
            unsigned h, l;
            split2b(v0.x, v1.x, h, l); Wp_hi[k2][q * 4 + 0] = h; Wp_lo[k2][q * 4 + 0] = l;
            split2b(v0.y, v1.y, h, l); Wp_hi[k2][q * 4 + 1] = h; Wp_lo[k2][q * 4 + 1] = l;
            split2b(v0.z, v1.z, h, l); Wp_hi[k2][q * 4 + 2] = h; Wp_lo[k2][q * 4 + 2] = l;
            split2b(v0.w, v1.w, h, l); Wp_hi[k2][q * 4 + 3] = h; Wp_lo[k2][q * 4 + 3] = l;
        }
        __syncthreads();

        int t4 = lane & 3;
        int g  = lane >> 2;
        unsigned ahi[MT][4], alo[MT][4];
        #pragma unroll
        for (int mt = 0; mt < MT; mt++) {
            int m = warp_m * (MT * 16) + mt * 16 + g;
            ahi[mt][0] = Ap_hi[t4][m];         alo[mt][0] = Ap_lo[t4][m];
            ahi[mt][1] = Ap_hi[t4][m + 8];     alo[mt][1] = Ap_lo[t4][m + 8];
            ahi[mt][2] = Ap_hi[t4 + 4][m];     alo[mt][2] = Ap_lo[t4 + 4][m];
            ahi[mt][3] = Ap_hi[t4 + 4][m + 8]; alo[mt][3] = Ap_lo[t4 + 4][m + 8];
        }
        #pragma unroll
        for (int nt = 0; nt < NT; nt++) {
            int n = warp_n * (NT * 8) + nt * 8 + g;
            unsigned bh0 = Wp_hi[t4][n], bh1 = Wp_hi[t4 + 4][n];
            unsigned bl0 = Wp_lo[t4][n], bl1 = Wp_lo[t4 + 4][n];
            #pragma unroll
            for (int mt = 0; mt < MT; mt++) {
                mma_bf16(c[mt][nt][0], c[mt][nt][1], c[mt][nt][2], c[mt][nt][3],
                         ahi[mt][0], ahi[mt][1], ahi[mt][2], ahi[mt][3], bh0, bh1);
                mma_bf16(c[mt][nt][0], c[mt][nt][1], c[mt][nt][2], c[mt][nt][3],
                         ahi[mt][0], ahi[mt][1], ahi[mt][2], ahi[mt][3], bl0, bl1);
                mma_bf16(c[mt][nt][0], c[mt][nt][1], c[mt][nt][2], c[mt][nt][3],
                         alo[mt][0], alo[mt][1], alo[mt][2], alo[mt][3], bh0, bh1);
            }
        }
        __syncthreads();
    }

    // epilogue: unscaled fp16 store (agg1 applies dinv[src])
    #pragma unroll
    for (int mt = 0; mt < MT; mt++) {
        int r0 = rb + warp_m * (MT * 16) + mt * 16 + (lane >> 2);
        int colb = warp_n * (NT * 8) + (lane & 3) * 2;
        #pragma unroll
        for (int half = 0; half < 2; half++) {
            int row = half ? (r0 + 8) : r0;
            int q0 = half * 2;
            if (row < NNODES) {
                #pragma unroll
                for (int nt = 0; nt < NT; nt++)
                    *(__half2*)&g_bufH[(size_t)row * FOUT + colb + nt * 8] =
                        __floats2half2_rn(c[mt][nt][q0], c[mt][nt][q0 + 1]);
            }
        }
    }
}

// ------- layer-2/3 GEMM: g_bufH = (g_bufG @ W) * dinv, fp16 A, 2-term W ------
template <int FOUT, int MW, int NW>
__global__ __launch_bounds__(256) void gemm_h_k(const float* __restrict__ W)
{
    const int BM = 128, BK = 16, K2 = BK / 2;
    const int MT = BM / (16 * MW);
    const int NT = FOUT / (8 * NW);
    const int APAD = BM + 8;
    const int WPAD = FOUT + 8;

    __shared__ unsigned Ap[K2][APAD];
    __shared__ unsigned Wp_hi[K2][WPAD], Wp_lo[K2][WPAD];

    int tid  = threadIdx.x;
    int lane = tid & 31;
    int wid  = tid >> 5;
    int warp_m = wid % MW;
    int warp_n = wid / MW;
    int rb = blockIdx.x * BM;

    float c[MT][NT][4];
    #pragma unroll
    for (int mt = 0; mt < MT; mt++)
        #pragma unroll
        for (int nt = 0; nt < NT; nt++)
            #pragma unroll
            for (int q = 0; q < 4; q++) c[mt][nt][q] = 0.0f;

    for (int kt = 0; kt < FIN; kt += BK) {
        // A tile: fp16 direct copy, 128 rows x 16 k = 256 uint4, 1/thread
        {
            int r = tid & 127, q = tid >> 7;       // q in {0,1}
            int row = rb + r;
            uint4 v = make_uint4(0, 0, 0, 0);
            if (row < NNODES)
                v = *(const uint4*)&g_bufG[(size_t)row * FIN + kt + q * 8];
            Ap[q * 4 + 0][r] = v.x;
            Ap[q * 4 + 1][r] = v.y;
            Ap[q * 4 + 2][r] = v.z;
            Ap[q * 4 + 3][r] = v.w;
        }
        // W tile: fp16 hi/lo split
        {
            int tasks = K2 * (FOUT / 4);
            if (tid < tasks) {
                int k2 = tid / (FOUT / 4), q = tid % (FOUT / 4);
                float4 v0 = *(const float4*)&W[(size_t)(kt + 2 * k2) * FOUT + q * 4];
                float4 v1 = *(const float4*)&W[(size_t)(kt + 2 * k2 + 1) * FOUT + q * 4];
                unsigned h, l;
                split2h(v0.x, v1.x, h, l); Wp_hi[k2][q * 4 + 0] = h; Wp_lo[k2][q * 4 + 0] = l;
                split2h(v0.y, v1.y, h, l); Wp_hi[k2][q * 4 + 1] = h; Wp_lo[k2][q * 4 + 1] = l;
                split2h(v0.z, v1.z, h, l); Wp_hi[k2][q * 4 + 2] = h; Wp_lo[k2][q * 4 + 2] = l;
                split2h(v0.w, v1.w, h, l); Wp_hi[k2][q * 4 + 3] = h; Wp_lo[k2][q * 4 + 3] = l;
            }
        }
        __syncthreads();

        int t4 = lane & 3;
        int g  = lane >> 2;
        unsigned a[MT][4];
        #pragma unroll
        for (int mt = 0; mt < MT; mt++) {
            int m = warp_m * (MT * 16) + mt * 16 + g;
            a[mt][0] = Ap[t4][m];
            a[mt][1] = Ap[t4][m + 8];
            a[mt][2] = Ap[t4 + 4][m];
            a[mt][3] = Ap[t4 + 4][m + 8];
        }
        #pragma unroll
        for (int nt = 0; nt < NT; nt++) {
            int n = warp_n * (NT * 8) + nt * 8 + g;
            unsigned bh0 = Wp_hi[t4][n], bh1 = Wp_hi[t4 + 4][n];
            unsigned bl0 = Wp_lo[t4][n], bl1 = Wp_lo[t4 + 4][n];
            #pragma unroll
            for (int mt = 0; mt < MT; mt++) {
                mma_f16(c[mt][nt][0], c[mt][nt][1], c[mt][nt][2], c[mt][nt][3],
                        a[mt][0], a[mt][1], a[mt][2], a[mt][3], bh0, bh1);
                mma_f16(c[mt][nt][0], c[mt][nt][1], c[mt][nt][2], c[mt][nt][3],
                        a[mt][0], a[mt][1], a[mt][2], a[mt][3], bl0, bl1);
            }
        }
        __syncthreads();
    }

    // epilogue: dinv scale, fp16 store
    #pragma unroll
    for (int mt = 0; mt < MT; mt++) {
        int r0 = rb + warp_m * (MT * 16) + mt * 16 + (lane >> 2);
        int colb = warp_n * (NT * 8) + (lane & 3) * 2;
        #pragma unroll
        for (int half = 0; half < 2; half++) {
            int row = half ? (r0 + 8) : r0;
            int q0 = half * 2;
            if (row < NNODES) {
                float d = g_dinv[row];
                #pragma unroll
                for (int nt = 0; nt < NT; nt++)
                    *(__half2*)&g_bufH[(size_t)row * FOUT + colb + nt * 8] =
                        __floats2half2_rn(c[mt][nt][q0] * d, c[mt][nt][q0 + 1] * d);
            }
        }
    }
}

// ---------------- aggregate fp16 hs (half-warp per dst, uint4/lane, F=128) ----
// SRCSCALE: hs holds unscaled h; multiply dinv[src] per edge (layer 1).
// Output: fp16 to g_bufG (next GEMM's A).
template <bool SRCSCALE>
__global__ __launch_bounds__(256) void agg128h_k(
    const float* __restrict__ bias,
    const float* __restrict__ gam, const float* __restrict__ bet,
    const float* __restrict__ mu,  const float* __restrict__ var)
{
    int dst  = blockIdx.x * 16 + (threadIdx.x >> 4);
    int lane = threadIdx.x & 15;
    if (dst >= NNODES) return;

    const uint4* hs = (const uint4*)g_bufH;   // row = 16 uint4 (8 fp16 each)

    int beg = g_rowptr[dst];
    int end = g_rowptr[dst + 1];
    float d = g_dinv[dst];

    float acc[8];
    {
        uint4 v = hs[(size_t)dst * 16 + lane];
        float2 f0 = __half22float2(*(__half2*)&v.x);
        float2 f1 = __half22float2(*(__half2*)&v.y);
        float2 f2 = __half22float2(*(__half2*)&v.z);
        float2 f3 = __half22float2(*(__half2*)&v.w);
        float sd = SRCSCALE ? d : 1.0f;
        acc[0] = f0.x * sd; acc[1] = f0.y * sd;
        acc[2] = f1.x * sd; acc[3] = f1.y * sd;
        acc[4] = f2.x * sd; acc[5] = f2.y * sd;
        acc[6] = f3.x * sd; acc[7] = f3.y * sd;
    }

    int e = beg;
    for (; e + 8 <= end; e += 8) {
        uint4 v[8]; float sc[8];
        #pragma unroll
        for (int u = 0; u < 8; u++) {
            int c = g_col[e + u];
            v[u] = hs[(size_t)c * 16 + lane];
            sc[u] = SRCSCALE ? g_dinv[c] : 1.0f;
        }
        #pragma unroll
        for (int u = 0; u < 8; u++) {
            float2 f0 = __half22float2(*(__half2*)&v[u].x);
            float2 f1 = __half22float2(*(__half2*)&v[u].y);
            float2 f2 = __half22float2(*(__half2*)&v[u].z);
            float2 f3 = __half22float2(*(__half2*)&v[u].w);
            acc[0] += f0.x * sc[u]; acc[1] += f0.y * sc[u];
            acc[2] += f1.x * sc[u]; acc[3] += f1.y * sc[u];
            acc[4] += f2.x * sc[u]; acc[5] += f2.y * sc[u];
            acc[6] += f3.x * sc[u]; acc[7] += f3.y * sc[u];
        }
    }
    for (; e < end; e++) {
        int c = g_col[e];
        uint4 v = hs[(size_t)c * 16 + lane];
        float sc = SRCSCALE ? g_dinv[c] : 1.0f;
        float2 f0 = __half22float2(*(__half2*)&v.x);
        float2 f1 = __half22float2(*(__half2*)&v.y);
        float2 f2 = __half22float2(*(__half2*)&v.z);
        float2 f3 = __half22float2(*(__half2*)&v.w);
        acc[0] += f0.x * sc; acc[1] += f0.y * sc;
        acc[2] += f1.x * sc; acc[3] += f1.y * sc;
        acc[4] += f2.x * sc; acc[5] += f2.y * sc;
        acc[6] += f3.x * sc; acc[7] += f3.y * sc;
    }

    float4 b0 = ((const float4*)bias)[lane * 2], b1 = ((const float4*)bias)[lane * 2 + 1];
    float4 g0 = ((const float4*)gam)[lane * 2],  g1 = ((const float4*)gam)[lane * 2 + 1];
    float4 t0 = ((const float4*)bet)[lane * 2],  t1 = ((const float4*)bet)[lane * 2 + 1];
    float4 m0 = ((const float4*)mu)[lane * 2],   m1 = ((const float4*)mu)[lane * 2 + 1];
    float4 v0 = ((const float4*)var)[lane * 2],  v1 = ((const float4*)var)[lane * 2 + 1];
    float bb[8] = {b0.x, b0.y, b0.z, b0.w, b1.x, b1.y, b1.z, b1.w};
    float gg[8] = {g0.x, g0.y, g0.z, g0.w, g1.x, g1.y, g1.z, g1.w};
    float tt[8] = {t0.x, t0.y, t0.z, t0.w, t1.x, t1.y, t1.z, t1.w};
    float mm[8] = {m0.x, m0.y, m0.z, m0.w, m1.x, m1.y, m1.z, m1.w};
    float vv[8] = {v0.x, v0.y, v0.z, v0.w, v1.x, v1.y, v1.z, v1.w};

    float r[8];
    #pragma unroll
    for (int q = 0; q < 8; q++) {
        float val = acc[q] * d + bb[q];
        val = (val - mm[q]) * rsqrtf(vv[q] + BN_EPS) * gg[q] + tt[q];
        r[q] = val > 0.f ? val : 0.1f * val;
    }
    uint4 o;
    *(__half2*)&o.x = __floats2half2_rn(r[0], r[1]);
    *(__half2*)&o.y = __floats2half2_rn(r[2], r[3]);
    *(__half2*)&o.z = __floats2half2_rn(r[4], r[5]);
    *(__half2*)&o.w = __floats2half2_rn(r[6], r[7]);
    ((uint4*)g_bufG)[(size_t)dst * 16 + lane] = o;
}

// ---------------- aggregate F=64 fp16 hs (half-warp per dst, uint2/lane) ------
__global__ __launch_bounds__(256) void agg64h_k(
    float* __restrict__ Oext, const float* __restrict__ bias)
{
    int dst  = blockIdx.x * 16 + (threadIdx.x >> 4);
    int lane = threadIdx.x & 15;
    if (dst >= NNODES) return;

    const uint2* hs = (const uint2*)g_bufH;   // row = 16 uint2 (4 fp16 each)

    int beg = g_rowptr[dst];
    int end = g_rowptr[dst + 1];

    float acc[4];
    {
        uint2 v = hs[(size_t)dst * 16 + lane];
        float2 f0 = __half22float2(*(__half2*)&v.x);
        float2 f1 = __half22float2(*(__half2*)&v.y);
        acc[0] = f0.x; acc[1] = f0.y; acc[2] = f1.x; acc[3] = f1.y;
    }
    int e = beg;
    for (; e + 8 <= end; e += 8) {
        uint2 v[8];
        #pragma unroll
        for (int u = 0; u < 8; u++)
            v[u] = hs[(size_t)g_col[e + u] * 16 + lane];
        #pragma unroll
        for (int u = 0; u < 8; u++) {
            float2 f0 = __half22float2(*(__half2*)&v[u].x);
            float2 f1 = __half22float2(*(__half2*)&v[u].y);
            acc[0] += f0.x; acc[1] += f0.y; acc[2] += f1.x; acc[3] += f1.y;
        }
    }
    for (; e < end; e++) {
        uint2 v = hs[(size_t)g_col[e] * 16 + lane];
        float2 f0 = __half22float2(*(__half2*)&v.x);
        float2 f1 = __half22float2(*(__half2*)&v.y);
        acc[0] += f0.x; acc[1] += f0.y; acc[2] += f1.x; acc[3] += f1.y;
    }

    float d = g_dinv[dst];
    float4 b4 = ((const float4*)bias)[lane];
    float4 r;
    r.x = acc[0] * d + b4.x;
    r.y = acc[1] * d + b4.y;
    r.z = acc[2] * d + b4.z;
    r.w = acc[3] * d + b4.w;
    ((float4*)Oext)[(size_t)dst * 16 + lane] = r;
}

// ---------------- launch ----------------
extern "C" void kernel_launch(void* const* d_in, const int* in_sizes, int n_in,
                              void* d_out, int out_size)
{
    const float* x   = (const float*)d_in[0];
    const int*   ei  = (const int*)d_in[1];
    const float* W1 = (const float*)d_in[2];
    const float* b1 = (const float*)d_in[3];
    const float* g1 = (const float*)d_in[4];
    const float* be1= (const float*)d_in[5];
    const float* m1 = (const float*)d_in[6];
    const float* v1 = (const float*)d_in[7];
    const float* W2 = (const float*)d_in[8];
    const float* b2 = (const float*)d_in[9];
    const float* g2 = (const float*)d_in[10];
    const float* be2= (const float*)d_in[11];
    const float* m2 = (const float*)d_in[12];
    const float* v2 = (const float*)d_in[13];
    const float* W3 = (const float*)d_in[14];
    const float* b3 = (const float*)d_in[15];
    float* out = (float*)d_out;

    // side stream + events, created once on the (non-captured) correctness call
    static cudaStream_t s2 = nullptr;
    static cudaEvent_t evF = nullptr, evJ = nullptr;
    if (s2 == nullptr) {
        cudaStreamCreateWithFlags(&s2, cudaStreamNonBlocking);
        cudaEventCreateWithFlags(&evF, cudaEventDisableTiming);
        cudaEventCreateWithFlags(&evJ, cudaEventDisableTiming);
    }

    const int gblk = (NNODES + 127) / 128;
    const int ablk = (NNODES + 15) / 16;

    // fork: CSR build on s2, concurrent with GEMM1 (g_deg is 0 at entry)
    cudaEventRecord(evF, 0);
    cudaStreamWaitEvent(s2, evF, 0);
    hist_rank_k<<<(NEDGES / 4 + 255) / 256, 256, 0, s2>>>(ei);
    scan1_k<<<NCHUNK, 256, 0, s2>>>();
    scanB_k<<<NCHUNK, 1024, 0, s2>>>();          // also re-zeroes g_deg
    scatter_k<<<(NEDGES / 4 + 255) / 256, 256, 0, s2>>>(ei);

    // layer 1 GEMM: x @ W1 -> g_bufH fp16 (unscaled)
    gemm1_k<<<gblk, 256>>>(x, W1);

    // join
    cudaEventRecord(evJ, s2);
    cudaStreamWaitEvent(0, evJ, 0);

    // layer 1 agg (applies dinv[src] inline), BN1 + leaky -> g_bufG fp16
    agg128h_k<true><<<ablk, 256>>>(b1, g1, be1, m1, v1);

    // layer 2: fp16 GEMM (g_bufG @ W2)*dinv -> g_bufH ; agg -> g_bufG
    gemm_h_k<128, 4, 2><<<gblk, 256>>>(W2);
    agg128h_k<false><<<ablk, 256>>>(b2, g2, be2, m2, v2);

    // layer 3: fp16 GEMM (g_bufG @ W3)*dinv -> g_bufH ; agg -> out fp32
    gemm_h_k<64, 8, 1><<<gblk, 256>>>(W3);
    agg64h_k<<<ablk, 256>>>(out, b3);
}